// round 6
// baseline (speedup 1.0000x reference)
#include <cuda_runtime.h>

#define NBLK 144
#define N0   54
#define N1   90
#define NTHR 1024
#define Bz   32
#define Ssz  2048
#define Isz  128
#define Hsz  512
#define Osz  128
#define K0   640
#define K1   1024
#define P0   644
#define PH   516

#define OFF_BIAS  0
#define OFF_PARTZ 64
#define OFF_PARTG 6464
#define OFF_PARTY 12608
#define OFF_STAGE 13632
#define OFF_W     34304
#define OFF_WY    54784
#define SMEM_FLOATS 56832
#define SMEM_BYTES (SMEM_FLOATS * 4)
#define BZ 0
#define BG 24
#define BY 40

__device__ float g_h0[2][Bz * Hsz];
__device__ float g_h1[2][Bz * Hsz];
__device__ float g_z0[Bz * Hsz];
__device__ float g_rh0[Bz * Hsz];
__device__ float g_z1[Bz * Hsz];
__device__ float g_rh1[Bz * Hsz];
__device__ unsigned g_count;

__device__ __forceinline__ float4 ldcg4(const float* p) {
    float4 v;
    asm volatile("ld.global.cg.v4.f32 {%0,%1,%2,%3}, [%4];"
                 : "=f"(v.x), "=f"(v.y), "=f"(v.z), "=f"(v.w) : "l"(p));
    return v;
}
__device__ __forceinline__ float ldcgf(const float* p) {
    float v;
    asm volatile("ld.global.cg.f32 %0, [%1];" : "=f"(v) : "l"(p));
    return v;
}
__device__ __forceinline__ void stcgf(float* p, float v) {
    asm volatile("st.global.cg.f32 [%0], %1;" :: "l"(p), "f"(v));
}

__device__ __forceinline__ void grid_sync(unsigned target) {
    __syncthreads();
    if (threadIdx.x == 0) {
        asm volatile("red.release.gpu.add.u32 [%0], %1;"
                     :: "l"(&g_count), "r"(1u) : "memory");
        unsigned v;
        do {
            asm volatile("ld.acquire.gpu.u32 %0, [%1];"
                         : "=r"(v) : "l"(&g_count) : "memory");
        } while (v < target);
    }
    __syncthreads();
}

__device__ __forceinline__ float sigmoid_(float x) { return 1.0f / (1.0f + __expf(-x)); }
__device__ __forceinline__ float tanh_(float x)    { return 1.0f - 2.0f / (__expf(2.0f * x) + 1.0f); }

__device__ __forceinline__ unsigned long long f2(unsigned long long w,
                                                 unsigned long long s,
                                                 unsigned long long acc) {
    unsigned long long d;
    asm("fma.rn.f32x2 %0, %1, %2, %3;" : "=l"(d) : "l"(w), "l"(s), "l"(acc));
    return d;
}

template <int KLEN, int ROWS, bool ACC>
__device__ __forceinline__ void dot_job(const float* __restrict__ wb, int wstride,
                                        const float* __restrict__ sb,
                                        float* __restrict__ pd, int prs) {
    unsigned long long acc[2 * ROWS];
#pragma unroll
    for (int i = 0; i < 2 * ROWS; ++i) acc[i] = 0ull;
#pragma unroll 2
    for (int k = 0; k < KLEN; k += 4) {
        ulonglong2 sv = *(const ulonglong2*)(sb + k);
#pragma unroll
        for (int r = 0; r < ROWS; ++r) {
            ulonglong2 wv = *(const ulonglong2*)(wb + r * wstride + k);
            acc[2 * r]     = f2(wv.x, sv.x, acc[2 * r]);
            acc[2 * r + 1] = f2(wv.y, sv.y, acc[2 * r + 1]);
        }
    }
#pragma unroll
    for (int r = 0; r < ROWS; ++r) {
        float2 a = *(float2*)&acc[2 * r];
        float2 b = *(float2*)&acc[2 * r + 1];
        float v = (a.x + a.y) + (b.x + b.y);
        if (ACC) pd[r * prs] += v; else pd[r * prs] = v;
    }
}

template <int KS, int KLEN, int KSLOTS, bool ACC>
__device__ __forceinline__ void run_jobs(const float* __restrict__ W, int wstride,
                                         int coloff, int NG8, int tail,
                                         const float* __restrict__ stg, int pitch,
                                         float* __restrict__ part) {
    const int lane = threadIdx.x & 31, wid = threadIdx.x >> 5;
    const int njobs = (NG8 + tail) * KS;
    for (int job = wid; job < njobs; job += 32) {
        const int g = job / KS, kq = job - g * KS;
        const float* wb = W + (g * 8) * wstride + coloff + kq * KLEN;
        const float* sb = stg + lane * pitch + kq * KLEN;
        float* pd = part + ((g * 8) * KSLOTS + kq) * 32 + lane;
        if (g < NG8) dot_job<KLEN, 8, ACC>(wb, wstride, sb, pd, KSLOTS * 32);
        else         dot_job<KLEN, 4, ACC>(wb, wstride, sb, pd, KSLOTS * 32);
    }
}

__global__ void reset_k() { g_count = 0u; }

extern "C" __global__ void __launch_bounds__(NTHR, 1)
gru_occ(const float* __restrict__ input, const float* __restrict__ h0in,
        const float* __restrict__ Wx0, const float* __restrict__ Wh0,
        const float* __restrict__ bh0, const float* __restrict__ Wx1,
        const float* __restrict__ Wh1, const float* __restrict__ bh1,
        const float* __restrict__ Why, const float* __restrict__ bhy,
        float* __restrict__ out) {
    extern __shared__ float sm[];
    const int tid = threadIdx.x;
    const bool l0 = (blockIdx.x < N0);
    const int q = l0 ? blockIdx.x : blockIdx.x - N0;

    int zr_lo, Rzr, gr_lo, Rg, y_lo = 0, Ry = 0;
    if (l0) {
        zr_lo = 4 * ((256 * q) / N0); Rzr = 4 * ((256 * (q + 1)) / N0) - zr_lo;
        gr_lo = 4 * ((128 * q) / N0); Rg  = 4 * ((128 * (q + 1)) / N0) - gr_lo;
    } else {
        zr_lo = 4 * ((256 * q) / N1); Rzr = 4 * ((256 * (q + 1)) / N1) - zr_lo;
        gr_lo = 4 * ((128 * q) / N1); Rg  = 4 * ((128 * (q + 1)) / N1) - gr_lo;
        y_lo = (Osz * q) / N1;        Ry  = (Osz * (q + 1)) / N1 - y_lo;
    }
    const int zNG8 = Rzr >> 3, zT = (Rzr & 7) ? 1 : 0;
    const int gNG8 = Rg >> 3,  gT = (Rg & 7) ? 1 : 0;

    float* bias  = sm + OFF_BIAS;
    float* partZ = sm + OFF_PARTZ;
    float* partG = sm + OFF_PARTG;
    float* partY = sm + OFF_PARTY;
    float* stg   = sm + OFF_STAGE;
    float* Wzr   = sm + OFF_W;
    float* Wg    = sm + OFF_W + (l0 ? 12800 : 12288);
    float* Wy    = sm + OFF_WY;

    if (l0) {
        for (int i = tid; i < Rzr * K0; i += NTHR) {
            int r = i / K0, k = i - r * K0, j = zr_lo + r;
            Wzr[i] = (k < Isz) ? Wx0[j * Isz + k] : Wh0[j * Hsz + k - Isz];
        }
        for (int i = tid; i < Rg * K0; i += NTHR) {
            int r = i / K0, k = i - r * K0, j = 2 * Hsz + gr_lo + r;
            Wg[i] = (k < Isz) ? Wx0[j * Isz + k] : Wh0[j * Hsz + k - Isz];
        }
        if (tid < Rzr) bias[BZ + tid] = bh0[zr_lo + tid];
        if (tid >= 32 && tid - 32 < Rg) bias[BG + tid - 32] = bh0[2 * Hsz + gr_lo + tid - 32];
    } else {
        for (int i = tid; i < Rzr * K1; i += NTHR) {
            int r = i >> 10, k = i & 1023, j = zr_lo + r;
            Wzr[i] = (k < Hsz) ? Wx1[j * Hsz + k] : Wh1[j * Hsz + k - Hsz];
        }
        for (int i = tid; i < Rg * K1; i += NTHR) {
            int r = i >> 10, k = i & 1023, j = 2 * Hsz + gr_lo + r;
            Wg[i] = (k < Hsz) ? Wx1[j * Hsz + k] : Wh1[j * Hsz + k - Hsz];
        }
        for (int i = tid; i < 4 * Hsz; i += NTHR) {
            int r = i >> 9, k = i & 511;
            Wy[i] = (r < Ry) ? Why[(y_lo + r) * Hsz + k] : 0.f;
        }
        if (tid < Rzr) bias[BZ + tid] = bh1[zr_lo + tid];
        if (tid >= 32 && tid - 32 < Rg) bias[BG + tid - 32] = bh1[2 * Hsz + gr_lo + tid - 32];
        if (tid >= 64 && tid - 64 < Ry) bias[BY + tid - 64] = bhy[y_lo + tid - 64];
    }
    {
        int i = blockIdx.x * NTHR + tid;
        if (i < Bz * 2 * Hsz) {
            int b = i >> 10, rest = i & 1023;
            float v = h0in[i];
            if (rest < Hsz) stcgf(&g_h0[0][b * Hsz + rest], v);
            else            stcgf(&g_h1[0][b * Hsz + rest - Hsz], v);
        }
    }
    unsigned bar = 0;
    grid_sync(++bar * NBLK);

    for (int tau = 0; tau <= Ssz; ++tau) {
        // ---------- PHASE 1 ----------
        if (l0) {
            if (tau < Ssz) {
                const int par = tau & 1;
                for (int i = tid; i < Bz * 32; i += NTHR) {
                    int b = i >> 5, k = (i & 31) << 2;
                    *(float4*)(stg + b * P0 + k) =
                        *(const float4*)(input + (b * Ssz + tau) * Isz + k);
                }
                for (int i = tid; i < Bz * 128; i += NTHR) {
                    int b = i >> 7, k = (i & 127) << 2;
                    *(float4*)(stg + b * P0 + Isz + k) = ldcg4(&g_h0[par][b * Hsz + k]);
                }
                __syncthreads();
                run_jobs<10, 64, 10, false>(Wzr, K0, 0, zNG8, zT, stg, P0, partZ);
                __syncthreads();
                for (int idx = tid; idx < Rzr * 32; idx += NTHR) {
                    int row = idx >> 5, b = idx & 31;
                    float acc = bias[BZ + row];
#pragma unroll
                    for (int kq = 0; kq < 10; ++kq) acc += partZ[(row * 10 + kq) * 32 + b];
                    float s = sigmoid_(acc);
                    int j = zr_lo + row;
                    if (j < Hsz) stcgf(&g_z0[b * Hsz + j], s);
                    else stcgf(&g_rh0[b * Hsz + j - Hsz], s * stg[b * P0 + Isz + (j - Hsz)]);
                }
            }
        } else {
            if (tau >= 1) {
                const int bo = tau & 1, bn = (tau + 1) & 1;
                for (int i = tid; i < Bz * 128; i += NTHR) {   // half A: h0'
                    int b = i >> 7, k = (i & 127) << 2;
                    *(float4*)(stg + b * PH + k) = ldcg4(&g_h0[bo][b * Hsz + k]);
                }
                __syncthreads();
                run_jobs<16, 32, 16, false>(Wzr, K1, 0, zNG8, zT, stg, PH, partZ);
                run_jobs<16, 32, 16, false>(Wg,  K1, 0, gNG8, gT, stg, PH, partG);
                __syncthreads();
                for (int i = tid; i < Bz * 128; i += NTHR) {   // half B: h1_old
                    int b = i >> 7, k = (i & 127) << 2;
                    *(float4*)(stg + b * PH + k) = ldcg4(&g_h1[bn][b * Hsz + k]);
                }
                __syncthreads();
                run_jobs<16, 32, 16, true>(Wzr, K1, 512, zNG8, zT, stg, PH, partZ);
                run_jobs<8, 64, 8, false>(Wy, 512, 0, 0, 1, stg, PH, partY);
                __syncthreads();
                for (int idx = tid; idx < Rzr * 32; idx += NTHR) {
                    int row = idx >> 5, b = idx & 31;
                    float acc = bias[BZ + row];
#pragma unroll
                    for (int kq = 0; kq < 16; ++kq) acc += partZ[(row * 16 + kq) * 32 + b];
                    float s = sigmoid_(acc);
                    int j = zr_lo + row;
                    if (j < Hsz) stcgf(&g_z1[b * Hsz + j], s);
                    else stcgf(&g_rh1[b * Hsz + j - Hsz], s * stg[b * PH + (j - Hsz)]);
                }
                if (tau >= 2) {
                    for (int idx = tid; idx < Ry * 32; idx += NTHR) {
                        int row = idx >> 5, b = idx & 31;
                        float acc = bias[BY + row];
#pragma unroll
                        for (int kq = 0; kq < 8; ++kq) acc += partY[(row * 8 + kq) * 32 + b];
                        out[(b * Ssz + (tau - 2)) * Osz + y_lo + row] = acc;
                    }
                }
            }
        }
        grid_sync(++bar * NBLK);

        // ---------- PHASE 2 ----------
        if (l0) {
            if (tau < Ssz) {
                const int par = tau & 1, nxt = par ^ 1;
                for (int i = tid; i < Bz * 128; i += NTHR) {
                    int b = i >> 7, k = (i & 127) << 2;
                    *(float4*)(stg + b * P0 + Isz + k) = ldcg4(&g_rh0[b * Hsz + k]);
                }
                __syncthreads();
                run_jobs<16, 40, 16, false>(Wg, K0, 0, gNG8, gT, stg, P0, partG);
                __syncthreads();
                for (int idx = tid; idx < Rg * 32; idx += NTHR) {
                    int row = idx >> 5, b = idx & 31;
                    float acc = bias[BG + row];
#pragma unroll
                    for (int kq = 0; kq < 16; ++kq) acc += partG[(row * 16 + kq) * 32 + b];
                    float g = tanh_(acc);
                    int u = gr_lo + row;
                    float z = ldcgf(&g_z0[b * Hsz + u]);
                    float h = ldcgf(&g_h0[par][b * Hsz + u]);
                    stcgf(&g_h0[nxt][b * Hsz + u], z * h + (1.f - z) * g);
                }
            }
        } else {
            if (tau >= 1) {
                const int bo = (tau + 1) & 1, bn = tau & 1;
                for (int i = tid; i < Bz * 128; i += NTHR) {
                    int b = i >> 7, k = (i & 127) << 2;
                    *(float4*)(stg + b * PH + k) = ldcg4(&g_rh1[b * Hsz + k]);
                }
                __syncthreads();
                run_jobs<16, 32, 16, true>(Wg, K1, 512, gNG8, gT, stg, PH, partG);
                __syncthreads();
                for (int idx = tid; idx < Rg * 32; idx += NTHR) {
                    int row = idx >> 5, b = idx & 31;
                    float acc = bias[BG + row];
#pragma unroll
                    for (int kq = 0; kq < 16; ++kq) acc += partG[(row * 16 + kq) * 32 + b];
                    float g = tanh_(acc);
                    int u = gr_lo + row;
                    float z = ldcgf(&g_z1[b * Hsz + u]);
                    float h = ldcgf(&g_h1[bo][b * Hsz + u]);
                    stcgf(&g_h1[bn][b * Hsz + u], z * h + (1.f - z) * g);
                }
            }
        }
        grid_sync(++bar * NBLK);
    }

    // ---------- Epilogue ----------
    if (!l0 && Ry > 0) {
        for (int idx = tid; idx < Ry * 32; idx += NTHR) {
            int row = idx >> 5, b = idx & 31;
            const float* wy = Wy + row * Hsz;
            float acc = bias[BY + row];
            for (int k = 0; k < Hsz; k += 4) {
                float4 h = ldcg4(&g_h1[0][b * Hsz + k]);
                float4 w = *(const float4*)(wy + k);
                acc = fmaf(w.x, h.x, fmaf(w.y, h.y, fmaf(w.z, h.z, fmaf(w.w, h.w, acc))));
            }
            out[(b * Ssz + (Ssz - 1)) * Osz + (y_lo + row)] = acc;
        }
    }
    {
        int i = blockIdx.x * NTHR + tid;
        if (i < Bz * 2 * Hsz) {
            int b = i >> 10, rest = i & 1023;
            float v = (rest < Hsz) ? ldcgf(&g_h0[0][b * Hsz + rest])
                                   : ldcgf(&g_h1[0][b * Hsz + rest - Hsz]);
            out[Bz * Ssz * Osz + i] = v;
        }
    }
}

extern "C" void kernel_launch(void* const* d_in, const int* in_sizes, int n_in,
                              void* d_out, int out_size) {
    cudaFuncSetAttribute(gru_occ,
                         cudaFuncAttributeMaxDynamicSharedMemorySize, SMEM_BYTES);
    reset_k<<<1, 1>>>();
    gru_occ<<<NBLK, NTHR, SMEM_BYTES>>>(
        (const float*)d_in[0], (const float*)d_in[1], (const float*)d_in[2],
        (const float*)d_in[3], (const float*)d_in[4], (const float*)d_in[5],
        (const float*)d_in[6], (const float*)d_in[7], (const float*)d_in[8],
        (const float*)d_in[9], (float*)d_out);
}

// round 7
// speedup vs baseline: 1.1854x; 1.1854x over previous
#include <cuda_runtime.h>

#define NBLK 144
#define N0   54
#define N1   90
#define NTHR 768
#define Bz   32
#define Ssz  2048
#define Isz  128
#define Hsz  512
#define Osz  128

#define OFF_BIAS  0
#define OFF_PARTZ 64
#define OFF_PARTG 10304
#define OFF_PARTY 16448
#define OFF_W     17472
#define SMEM_FLOATS 40000
#define SMEM_BYTES (SMEM_FLOATS * 4)
#define BZ 0
#define BG 24
#define BY 40

// pair-interleaved k-major state: idx(k,b) = (k>>1)*64 + 2b + (k&1)
__device__ float g_h0[2][Bz * Hsz];
__device__ float g_h1[2][Bz * Hsz];
__device__ float g_z0[Bz * Hsz];
__device__ float g_rh0[Bz * Hsz];
__device__ float g_z1[Bz * Hsz];
__device__ float g_rh1[Bz * Hsz];
__device__ float g_xT[Ssz * 128 * Bz];   // [t][k>>1][2b+(k&1)]
__device__ unsigned g_count;

__device__ __forceinline__ int pidx(int k, int b) {
    return ((k >> 1) << 6) + (b << 1) + (k & 1);
}
__device__ __forceinline__ unsigned long long ldcg64(const float* p) {
    unsigned long long v;
    asm volatile("ld.global.cg.b64 %0, [%1];" : "=l"(v) : "l"(p));
    return v;
}
__device__ __forceinline__ float ldcgf(const float* p) {
    float v;
    asm volatile("ld.global.cg.f32 %0, [%1];" : "=f"(v) : "l"(p));
    return v;
}
__device__ __forceinline__ void stcgf(float* p, float v) {
    asm volatile("st.global.cg.f32 [%0], %1;" :: "l"(p), "f"(v));
}
__device__ __forceinline__ void grid_sync(unsigned target) {
    __syncthreads();
    if (threadIdx.x == 0) {
        asm volatile("red.release.gpu.add.u32 [%0], %1;"
                     :: "l"(&g_count), "r"(1u) : "memory");
        unsigned v;
        do {
            asm volatile("ld.acquire.gpu.u32 %0, [%1];"
                         : "=r"(v) : "l"(&g_count) : "memory");
        } while (v < target);
    }
    __syncthreads();
}
__device__ __forceinline__ float sigmoid_(float x) { return 1.0f / (1.0f + __expf(-x)); }
__device__ __forceinline__ float tanh_(float x)    { return 1.0f - 2.0f / (__expf(2.0f * x) + 1.0f); }
__device__ __forceinline__ unsigned long long f2(unsigned long long w,
                                                 unsigned long long s,
                                                 unsigned long long acc) {
    unsigned long long d;
    asm("fma.rn.f32x2 %0, %1, %2, %3;" : "=l"(d) : "l"(w), "l"(s), "l"(acc));
    return d;
}

// one job: ROWS rows x 64 k; state pairs direct from L2 (coalesced b64)
template <int ROWS>
__device__ __forceinline__ void dot_jobG(const float* __restrict__ wb, int wstride,
                                         const float* __restrict__ sg,
                                         float* __restrict__ pd, int prs) {
    unsigned long long acc[2 * ROWS];
#pragma unroll
    for (int i = 0; i < 2 * ROWS; ++i) acc[i] = 0ull;
#pragma unroll 4
    for (int k = 0; k < 64; k += 4) {
        unsigned long long sv0 = ldcg64(sg + (k >> 1) * 64);
        unsigned long long sv1 = ldcg64(sg + (k >> 1) * 64 + 64);
#pragma unroll
        for (int r = 0; r < ROWS; ++r) {
            ulonglong2 wv = *(const ulonglong2*)(wb + r * wstride + k);
            acc[2 * r]     = f2(wv.x, sv0, acc[2 * r]);
            acc[2 * r + 1] = f2(wv.y, sv1, acc[2 * r + 1]);
        }
    }
#pragma unroll
    for (int r = 0; r < ROWS; ++r) {
        float2 a = *(float2*)&acc[2 * r];
        float2 b = *(float2*)&acc[2 * r + 1];
        pd[r * prs] = (a.x + a.y) + (b.x + b.y);
    }
}

// pass: (NG8 8-row groups + tail 4-row) x KS k-chunks of 64; region A for kq<SPLIT else B
template <int KS, int SPLIT, int SLOTS>
__device__ __forceinline__ void runpass(const float* __restrict__ W, int wstride,
                                        int coloff, int NG8, int tail,
                                        const float* __restrict__ pA,
                                        const float* __restrict__ pB,
                                        float* __restrict__ part, int slotbase,
                                        int woff) {
    const int lane = threadIdx.x & 31;
    int wid = (threadIdx.x >> 5) - woff;
    if (wid < 0) wid += 24;
    const int njobs = (NG8 + tail) * KS;
    for (int job = wid; job < njobs; job += 24) {
        const int g = job / KS, kq = job - g * KS;
        const float* sg = (kq < SPLIT ? pA + kq * 2048
                                      : pB + (kq - SPLIT) * 2048) + 2 * lane;
        const float* wb = W + (g * 8) * wstride + coloff + kq * 64;
        float* pd = part + ((g * 8) * SLOTS + slotbase + kq) * 32 + lane;
        if (g < NG8) dot_jobG<8>(wb, wstride, sg, pd, SLOTS * 32);
        else         dot_jobG<4>(wb, wstride, sg, pd, SLOTS * 32);
    }
}

__global__ void prep_k(const float* __restrict__ input) {
    long long idx = (long long)blockIdx.x * 1024 + threadIdx.x;
    if (idx == 0) g_count = 0u;
    if (idx < (long long)Bz * Ssz * Isz) {
        int b = (int)(idx >> 18);
        int rem = (int)(idx & 262143);
        int t = rem >> 7, k = rem & 127;
        g_xT[t * 4096 + pidx(k, b)] = input[idx];
    }
}

extern "C" __global__ void __launch_bounds__(NTHR, 1)
gru_l2(const float* __restrict__ input, const float* __restrict__ h0in,
       const float* __restrict__ Wx0, const float* __restrict__ Wh0,
       const float* __restrict__ bh0, const float* __restrict__ Wx1,
       const float* __restrict__ Wh1, const float* __restrict__ bh1,
       const float* __restrict__ Why, const float* __restrict__ bhy,
       float* __restrict__ out) {
    extern __shared__ float sm[];
    const int tid = threadIdx.x;
    const bool l0 = (blockIdx.x < N0);
    const int q = l0 ? blockIdx.x : blockIdx.x - N0;

    int zr_lo, Rzr, gr_lo, Rg, y_lo = 0, Ry = 0;
    if (l0) {
        zr_lo = 4 * ((256 * q) / N0); Rzr = 4 * ((256 * (q + 1)) / N0) - zr_lo;
        gr_lo = 4 * ((128 * q) / N0); Rg  = 4 * ((128 * (q + 1)) / N0) - gr_lo;
    } else {
        zr_lo = 4 * ((256 * q) / N1); Rzr = 4 * ((256 * (q + 1)) / N1) - zr_lo;
        gr_lo = 4 * ((128 * q) / N1); Rg  = 4 * ((128 * (q + 1)) / N1) - gr_lo;
        y_lo = (Osz * q) / N1;        Ry  = (Osz * (q + 1)) / N1 - y_lo;
    }
    const int zNG8 = Rzr >> 3, zT = (Rzr & 7) ? 1 : 0;
    const int gNG8 = Rg >> 3,  gT = (Rg & 7) ? 1 : 0;
    const int KW = l0 ? 640 : 1024;

    float* bias  = sm + OFF_BIAS;
    float* partZ = sm + OFF_PARTZ;
    float* partG = sm + OFF_PARTG;
    float* partY = sm + OFF_PARTY;
    float* Wzr   = sm + OFF_W;
    float* Wg    = Wzr + Rzr * KW;
    float* Wy    = Wg + Rg * KW;    // L1 only

    // ---- weights ----
    if (l0) {
        for (int i = tid; i < Rzr * 640; i += NTHR) {
            int r = i / 640, k = i - r * 640, j = zr_lo + r;
            Wzr[i] = (k < Isz) ? Wx0[j * Isz + k] : Wh0[j * Hsz + k - Isz];
        }
        for (int i = tid; i < Rg * 640; i += NTHR) {
            int r = i / 640, k = i - r * 640, j = 2 * Hsz + gr_lo + r;
            Wg[i] = (k < Isz) ? Wx0[j * Isz + k] : Wh0[j * Hsz + k - Isz];
        }
        if (tid < Rzr) bias[BZ + tid] = bh0[zr_lo + tid];
        if (tid >= 32 && tid - 32 < Rg) bias[BG + tid - 32] = bh0[2 * Hsz + gr_lo + tid - 32];
    } else {
        for (int i = tid; i < Rzr * 1024; i += NTHR) {
            int r = i >> 10, k = i & 1023, j = zr_lo + r;
            Wzr[i] = (k < Hsz) ? Wx1[j * Hsz + k] : Wh1[j * Hsz + k - Hsz];
        }
        for (int i = tid; i < Rg * 1024; i += NTHR) {
            int r = i >> 10, k = i & 1023, j = 2 * Hsz + gr_lo + r;
            Wg[i] = (k < Hsz) ? Wx1[j * Hsz + k] : Wh1[j * Hsz + k - Hsz];
        }
        for (int i = tid; i < 4 * Hsz; i += NTHR) {
            int r = i >> 9, k = i & 511;
            Wy[i] = (r < Ry) ? Why[(y_lo + r) * Hsz + k] : 0.f;
        }
        if (tid < Rzr) bias[BZ + tid] = bh1[zr_lo + tid];
        if (tid >= 32 && tid - 32 < Rg) bias[BG + tid - 32] = bh1[2 * Hsz + gr_lo + tid - 32];
        if (tid >= 64 && tid - 64 < 4) bias[BY + tid - 64] = (tid - 64 < Ry) ? bhy[y_lo + tid - 64] : 0.f;
    }
    // ---- init state ----
    {
        int i = blockIdx.x * NTHR + tid;
        if (i < Bz * 2 * Hsz) {
            int b = i >> 10, rest = i & 1023;
            float v = h0in[i];
            if (rest < Hsz) stcgf(&g_h0[0][pidx(rest, b)], v);
            else            stcgf(&g_h1[0][pidx(rest - Hsz, b)], v);
        }
    }
    unsigned bar = 0;
    grid_sync(++bar * NBLK);

    for (int tau = 0; tau <= Ssz; ++tau) {
        // ---------------- PHASE 1 ----------------
        if (l0) {
            if (tau < Ssz) {
                const int par = tau & 1;
                const float* xT = g_xT + tau * 4096;
                const float* h0o = g_h0[par];
                // zr: KS=10 (kq<2 x, else h); gX: KS=2 on x only
                runpass<10, 2, 16>(Wzr, 640, 0, zNG8, zT, xT, h0o, partZ, 0, 0);
                runpass<2, 2, 16>(Wg, 640, 0, gNG8, gT, xT, xT, partG, 0, 6);
                __syncthreads();
                for (int idx = tid; idx < Rzr * 32; idx += NTHR) {
                    int row = idx >> 5, b = idx & 31;
                    float acc = bias[BZ + row];
#pragma unroll
                    for (int kq = 0; kq < 10; ++kq) acc += partZ[(row * 16 + kq) * 32 + b];
                    float s = sigmoid_(acc);
                    int j = zr_lo + row;
                    if (j < Hsz) stcgf(&g_z0[pidx(j, b)], s);
                    else {
                        float h = ldcgf(&g_h0[par][pidx(j - Hsz, b)]);
                        stcgf(&g_rh0[pidx(j - Hsz, b)], s * h);
                    }
                }
            }
        } else {
            if (tau >= 1) {
                const int bo = tau & 1, bn = (tau + 1) & 1;
                const float* h0n = g_h0[bo];
                const float* h1o = g_h1[bn];
                runpass<16, 8, 16>(Wzr, 1024, 0, zNG8, zT, h0n, h1o, partZ, 0, 0);
                runpass<8, 8, 16>(Wg, 1024, 0, gNG8, gT, h0n, h0n, partG, 0, 8);
                runpass<8, 8, 8>(Wy, 512, 0, 0, 1, h1o, h1o, partY, 0, 16);
                __syncthreads();
                for (int idx = tid; idx < Rzr * 32; idx += NTHR) {
                    int row = idx >> 5, b = idx & 31;
                    float acc = bias[BZ + row];
#pragma unroll
                    for (int kq = 0; kq < 16; ++kq) acc += partZ[(row * 16 + kq) * 32 + b];
                    float s = sigmoid_(acc);
                    int j = zr_lo + row;
                    if (j < Hsz) stcgf(&g_z1[pidx(j, b)], s);
                    else {
                        float h = ldcgf(&g_h1[bn][pidx(j - Hsz, b)]);
                        stcgf(&g_rh1[pidx(j - Hsz, b)], s * h);
                    }
                }
                if (tau >= 2) {
                    for (int idx = tid; idx < Ry * 32; idx += NTHR) {
                        int row = idx >> 5, b = idx & 31;
                        float acc = bias[BY + row];
#pragma unroll
                        for (int kq = 0; kq < 8; ++kq) acc += partY[(row * 8 + kq) * 32 + b];
                        out[(b * Ssz + (tau - 2)) * Osz + y_lo + row] = acc;
                    }
                }
            }
        }
        grid_sync(++bar * NBLK);

        // ---------------- PHASE 2 ----------------
        if (l0) {
            if (tau < Ssz) {
                const int par = tau & 1, nxt = par ^ 1;
                runpass<8, 8, 16>(Wg, 640, Isz, gNG8, gT, g_rh0, g_rh0, partG, 2, 0);
                __syncthreads();
                for (int idx = tid; idx < Rg * 32; idx += NTHR) {
                    int row = idx >> 5, b = idx & 31;
                    float acc = bias[BG + row];
#pragma unroll
                    for (int kq = 0; kq < 10; ++kq) acc += partG[(row * 16 + kq) * 32 + b];
                    float g = tanh_(acc);
                    int u = gr_lo + row;
                    float z = ldcgf(&g_z0[pidx(u, b)]);
                    float h = ldcgf(&g_h0[par][pidx(u, b)]);
                    stcgf(&g_h0[nxt][pidx(u, b)], z * h + (1.f - z) * g);
                }
            }
        } else {
            if (tau >= 1) {
                const int bo = (tau + 1) & 1, bn = tau & 1;
                runpass<8, 8, 16>(Wg, 1024, Hsz, gNG8, gT, g_rh1, g_rh1, partG, 8, 0);
                __syncthreads();
                for (int idx = tid; idx < Rg * 32; idx += NTHR) {
                    int row = idx >> 5, b = idx & 31;
                    float acc = bias[BG + row];
#pragma unroll
                    for (int kq = 0; kq < 16; ++kq) acc += partG[(row * 16 + kq) * 32 + b];
                    float g = tanh_(acc);
                    int u = gr_lo + row;
                    float z = ldcgf(&g_z1[pidx(u, b)]);
                    float h = ldcgf(&g_h1[bo][pidx(u, b)]);
                    stcgf(&g_h1[bn][pidx(u, b)], z * h + (1.f - z) * g);
                }
            }
        }
        grid_sync(++bar * NBLK);
    }

    // ---------------- Epilogue ----------------
    if (!l0 && Ry > 0) {
        for (int idx = tid; idx < Ry * 32; idx += NTHR) {
            int row = idx >> 5, b = idx & 31;
            const float* wy = Wy + row * Hsz;
            float acc = bias[BY + row];
            for (int k = 0; k < Hsz; k += 2) {
                unsigned long long sv = ldcg64(&g_h1[0][(k >> 1) * 64 + 2 * b]);
                float2 s = *(float2*)&sv;
                acc = fmaf(wy[k], s.x, fmaf(wy[k + 1], s.y, acc));
            }
            out[(b * Ssz + (Ssz - 1)) * Osz + (y_lo + row)] = acc;
        }
    }
    {
        int i = blockIdx.x * NTHR + tid;
        if (i < Bz * 2 * Hsz) {
            int b = i >> 10, rest = i & 1023;
            float v = (rest < Hsz) ? ldcgf(&g_h0[0][pidx(rest, b)])
                                   : ldcgf(&g_h1[0][pidx(rest - Hsz, b)]);
            out[Bz * Ssz * Osz + i] = v;
        }
    }
}

extern "C" void kernel_launch(void* const* d_in, const int* in_sizes, int n_in,
                              void* d_out, int out_size) {
    cudaFuncSetAttribute(gru_l2,
                         cudaFuncAttributeMaxDynamicSharedMemorySize, SMEM_BYTES);
    prep_k<<<8192, 1024>>>((const float*)d_in[0]);
    gru_l2<<<NBLK, NTHR, SMEM_BYTES>>>(
        (const float*)d_in[0], (const float*)d_in[1], (const float*)d_in[2],
        (const float*)d_in[3], (const float*)d_in[4], (const float*)d_in[5],
        (const float*)d_in[6], (const float*)d_in[7], (const float*)d_in[8],
        (const float*)d_in[9], (float*)d_out);
}

// round 8
// speedup vs baseline: 1.2118x; 1.0223x over previous
#include <cuda_runtime.h>

#define NBLK 144
#define N0   54
#define N1   90
#define NTHR 768
#define Bz   32
#define Ssz  2048
#define Isz  128
#define Hsz  512
#define Osz  128

#define OFF_BIAS  0
#define OFF_PARTZ 64
#define OFF_PARTG 20544
#define OFF_PARTY 32832
#define OFF_W     34880
#define SMEM_FLOATS 57408
#define SMEM_BYTES (SMEM_FLOATS * 4)
#define BZ 0
#define BG 24
#define BY 40

// pair-interleaved k-major: idx(k,b) = (k>>1)*64 + 2b + (k&1)
__device__ float g_h0[2][Bz * Hsz];
__device__ float g_h1[2][Bz * Hsz];
__device__ float g_z0[Bz * Hsz];
__device__ float g_rh0[Bz * Hsz];
__device__ float g_z1[Bz * Hsz];
__device__ float g_rh1[Bz * Hsz];
__device__ float g_xT[Ssz * 128 * Bz];
__device__ unsigned g_count;

__device__ __forceinline__ int pidx(int k, int b) {
    return ((k >> 1) << 6) + (b << 1) + (k & 1);
}
__device__ __forceinline__ unsigned long long ldcg64(const float* p) {
    unsigned long long v;
    asm volatile("ld.global.cg.b64 %0, [%1];" : "=l"(v) : "l"(p));
    return v;
}
__device__ __forceinline__ float ldcgf(const float* p) {
    float v;
    asm volatile("ld.global.cg.f32 %0, [%1];" : "=f"(v) : "l"(p));
    return v;
}
__device__ __forceinline__ void stcgf(float* p, float v) {
    asm volatile("st.global.cg.f32 [%0], %1;" :: "l"(p), "f"(v));
}
__device__ __forceinline__ void grid_sync(unsigned target) {
    __syncthreads();
    if (threadIdx.x == 0) {
        asm volatile("red.release.gpu.add.u32 [%0], %1;"
                     :: "l"(&g_count), "r"(1u) : "memory");
        unsigned v;
        do {
            asm volatile("ld.acquire.gpu.u32 %0, [%1];"
                         : "=r"(v) : "l"(&g_count) : "memory");
        } while (v < target);
    }
    __syncthreads();
}
__device__ __forceinline__ float sigmoid_(float x) { return 1.0f / (1.0f + __expf(-x)); }
__device__ __forceinline__ float tanh_(float x)    { return 1.0f - 2.0f / (__expf(2.0f * x) + 1.0f); }
__device__ __forceinline__ unsigned long long f2(unsigned long long w,
                                                 unsigned long long s,
                                                 unsigned long long acc) {
    unsigned long long d;
    asm("fma.rn.f32x2 %0, %1, %2, %3;" : "=l"(d) : "l"(w), "l"(s), "l"(acc));
    return d;
}

// job: ROWS rows x 32 k. Entire state slice burst-loaded first (MLP=16).
template <int ROWS>
__device__ __forceinline__ void dot_jobG(const float* __restrict__ wb, int wstride,
                                         const float* __restrict__ sg,
                                         float* __restrict__ pd, int prs) {
    unsigned long long s[16];
#pragma unroll
    for (int p = 0; p < 16; ++p) s[p] = ldcg64(sg + (p << 6));
    unsigned long long acc[ROWS];
#pragma unroll
    for (int r = 0; r < ROWS; ++r) acc[r] = 0ull;
#pragma unroll
    for (int p = 0; p < 16; p += 2) {
#pragma unroll
        for (int r = 0; r < ROWS; ++r) {
            ulonglong2 wv = *(const ulonglong2*)(wb + r * wstride + (p << 1));
            acc[r] = f2(wv.x, s[p], acc[r]);
            acc[r] = f2(wv.y, s[p + 1], acc[r]);
        }
    }
#pragma unroll
    for (int r = 0; r < ROWS; ++r) {
        float2 a = *(float2*)&acc[r];
        pd[r * prs] = a.x + a.y;
    }
}

// pass: (NG8 8-row groups + tail 4-row) x KS 32k-chunks; chunk kq<SPLIT in region A
template <int KS, int SPLIT>
__device__ __forceinline__ void runpass(const float* __restrict__ W, int wstride,
                                        int coloff, int NG8, int tail,
                                        const float* __restrict__ pA,
                                        const float* __restrict__ pB,
                                        float* __restrict__ part, int slotbase,
                                        int rowstride, int woff) {
    const int lane = threadIdx.x & 31;
    int wid = (threadIdx.x >> 5) - woff;
    if (wid < 0) wid += 24;
    const int njobs = (NG8 + tail) * KS;
    for (int job = wid; job < njobs; job += 24) {
        const int g = job / KS, kq = job - g * KS;
        const float* sg = (kq < SPLIT ? pA + kq * 1024
                                      : pB + (kq - SPLIT) * 1024) + 2 * lane;
        const float* wb = W + (g * 8) * wstride + coloff + (kq << 5);
        float* pd = part + ((g * 8) * rowstride + slotbase + kq) * 32 + lane;
        if (g < NG8) dot_jobG<8>(wb, wstride, sg, pd, rowstride * 32);
        else         dot_jobG<4>(wb, wstride, sg, pd, rowstride * 32);
    }
}

__global__ void prep_k(const float* __restrict__ input) {
    long long idx = (long long)blockIdx.x * 1024 + threadIdx.x;
    if (idx == 0) g_count = 0u;
    if (idx < (long long)Bz * Ssz * Isz) {
        int b = (int)(idx >> 18);
        int rem = (int)(idx & 262143);
        int t = rem >> 7, k = rem & 127;
        g_xT[t * 4096 + pidx(k, b)] = input[idx];
    }
}

extern "C" __global__ void __launch_bounds__(NTHR, 1)
gru_mlp(const float* __restrict__ input, const float* __restrict__ h0in,
        const float* __restrict__ Wx0, const float* __restrict__ Wh0,
        const float* __restrict__ bh0, const float* __restrict__ Wx1,
        const float* __restrict__ Wh1, const float* __restrict__ bh1,
        const float* __restrict__ Why, const float* __restrict__ bhy,
        float* __restrict__ out) {
    extern __shared__ float sm[];
    const int tid = threadIdx.x;
    const bool l0 = (blockIdx.x < N0);
    const int q = l0 ? blockIdx.x : blockIdx.x - N0;

    int zr_lo, Rzr, gr_lo, Rg, y_lo = 0, Ry = 0;
    if (l0) {
        zr_lo = 4 * ((256 * q) / N0); Rzr = 4 * ((256 * (q + 1)) / N0) - zr_lo;
        gr_lo = 4 * ((128 * q) / N0); Rg  = 4 * ((128 * (q + 1)) / N0) - gr_lo;
    } else {
        zr_lo = 4 * ((256 * q) / N1); Rzr = 4 * ((256 * (q + 1)) / N1) - zr_lo;
        gr_lo = 4 * ((128 * q) / N1); Rg  = 4 * ((128 * (q + 1)) / N1) - gr_lo;
        y_lo = (Osz * q) / N1;        Ry  = (Osz * (q + 1)) / N1 - y_lo;
    }
    const int zNG8 = Rzr >> 3, zT = (Rzr & 7) ? 1 : 0;
    const int gNG8 = Rg >> 3,  gT = (Rg & 7) ? 1 : 0;
    const int KW = l0 ? 640 : 1024;

    float* bias  = sm + OFF_BIAS;
    float* partZ = sm + OFF_PARTZ;
    float* partG = sm + OFF_PARTG;
    float* partY = sm + OFF_PARTY;
    float* Wzr   = sm + OFF_W;
    float* Wg    = Wzr + Rzr * KW;
    float* Wy    = Wg + Rg * KW;

    if (l0) {
        for (int i = tid; i < Rzr * 640; i += NTHR) {
            int r = i / 640, k = i - r * 640, j = zr_lo + r;
            Wzr[i] = (k < Isz) ? Wx0[j * Isz + k] : Wh0[j * Hsz + k - Isz];
        }
        for (int i = tid; i < Rg * 640; i += NTHR) {
            int r = i / 640, k = i - r * 640, j = 2 * Hsz + gr_lo + r;
            Wg[i] = (k < Isz) ? Wx0[j * Isz + k] : Wh0[j * Hsz + k - Isz];
        }
        if (tid < Rzr) bias[BZ + tid] = bh0[zr_lo + tid];
        if (tid >= 32 && tid - 32 < Rg) bias[BG + tid - 32] = bh0[2 * Hsz + gr_lo + tid - 32];
    } else {
        for (int i = tid; i < Rzr * 1024; i += NTHR) {
            int r = i >> 10, k = i & 1023, j = zr_lo + r;
            Wzr[i] = (k < Hsz) ? Wx1[j * Hsz + k] : Wh1[j * Hsz + k - Hsz];
        }
        for (int i = tid; i < Rg * 1024; i += NTHR) {
            int r = i >> 10, k = i & 1023, j = 2 * Hsz + gr_lo + r;
            Wg[i] = (k < Hsz) ? Wx1[j * Hsz + k] : Wh1[j * Hsz + k - Hsz];
        }
        for (int i = tid; i < 4 * Hsz; i += NTHR) {
            int r = i >> 9, k = i & 511;
            Wy[i] = (r < Ry) ? Why[(y_lo + r) * Hsz + k] : 0.f;
        }
        if (tid < Rzr) bias[BZ + tid] = bh1[zr_lo + tid];
        if (tid >= 32 && tid - 32 < Rg) bias[BG + tid - 32] = bh1[2 * Hsz + gr_lo + tid - 32];
        if (tid >= 64 && tid - 64 < 4) bias[BY + tid - 64] = (tid - 64 < Ry) ? bhy[y_lo + tid - 64] : 0.f;
    }
    {
        int i = blockIdx.x * NTHR + tid;
        if (i < Bz * 2 * Hsz) {
            int b = i >> 10, rest = i & 1023;
            float v = h0in[i];
            if (rest < Hsz) stcgf(&g_h0[0][pidx(rest, b)], v);
            else            stcgf(&g_h1[0][pidx(rest - Hsz, b)], v);
        }
    }
    unsigned bar = 0;
    grid_sync(++bar * NBLK);

    for (int tau = 0; tau <= Ssz; ++tau) {
        // ---------------- PHASE 1 ----------------
        if (l0) {
            if (tau < Ssz) {
                const int par = tau & 1;
                const float* xT = g_xT + tau * 4096;
                const float* h0o = g_h0[par];
                runpass<20, 4>(Wzr, 640, 0, zNG8, zT, xT, h0o, partZ, 0, 32, 0);
                runpass<4, 4>(Wg, 640, 0, gNG8, gT, xT, xT, partG, 0, 32, 8);
                __syncthreads();
                for (int idx = tid; idx < Rzr * 32; idx += NTHR) {
                    int row = idx >> 5, b = idx & 31;
                    float acc = bias[BZ + row];
#pragma unroll
                    for (int kq = 0; kq < 20; ++kq) acc += partZ[(row * 32 + kq) * 32 + b];
                    float s = sigmoid_(acc);
                    int j = zr_lo + row;
                    if (j < Hsz) stcgf(&g_z0[pidx(j, b)], s);
                    else {
                        float h = ldcgf(&g_h0[par][pidx(j - Hsz, b)]);
                        stcgf(&g_rh0[pidx(j - Hsz, b)], s * h);
                    }
                }
            }
        } else {
            if (tau >= 1) {
                const int bo = tau & 1, bn = (tau + 1) & 1;
                const float* h0n = g_h0[bo];
                const float* h1o = g_h1[bn];
                runpass<32, 16>(Wzr, 1024, 0, zNG8, zT, h0n, h1o, partZ, 0, 32, 0);
                runpass<16, 16>(Wg, 1024, 0, gNG8, gT, h0n, h0n, partG, 0, 32, 8);
                runpass<16, 16>(Wy, 512, 0, 0, 1, h1o, h1o, partY, 0, 16, 16);
                __syncthreads();
                for (int idx = tid; idx < Rzr * 32; idx += NTHR) {
                    int row = idx >> 5, b = idx & 31;
                    float acc = bias[BZ + row];
#pragma unroll
                    for (int kq = 0; kq < 32; ++kq) acc += partZ[(row * 32 + kq) * 32 + b];
                    float s = sigmoid_(acc);
                    int j = zr_lo + row;
                    if (j < Hsz) stcgf(&g_z1[pidx(j, b)], s);
                    else {
                        float h = ldcgf(&g_h1[bn][pidx(j - Hsz, b)]);
                        stcgf(&g_rh1[pidx(j - Hsz, b)], s * h);
                    }
                }
                if (tau >= 2) {
                    for (int idx = tid; idx < Ry * 32; idx += NTHR) {
                        int row = idx >> 5, b = idx & 31;
                        float acc = bias[BY + row];
#pragma unroll
                        for (int kq = 0; kq < 16; ++kq) acc += partY[(row * 16 + kq) * 32 + b];
                        out[(b * Ssz + (tau - 2)) * Osz + y_lo + row] = acc;
                    }
                }
            }
        }
        grid_sync(++bar * NBLK);

        // ---------------- PHASE 2 ----------------
        if (l0) {
            if (tau < Ssz) {
                const int par = tau & 1, nxt = par ^ 1;
                runpass<16, 16>(Wg, 640, Isz, gNG8, gT, g_rh0, g_rh0, partG, 4, 32, 0);
                __syncthreads();
                for (int idx = tid; idx < Rg * 32; idx += NTHR) {
                    int row = idx >> 5, b = idx & 31;
                    float acc = bias[BG + row];
#pragma unroll
                    for (int kq = 0; kq < 20; ++kq) acc += partG[(row * 32 + kq) * 32 + b];
                    float g = tanh_(acc);
                    int u = gr_lo + row;
                    float z = ldcgf(&g_z0[pidx(u, b)]);
                    float h = ldcgf(&g_h0[par][pidx(u, b)]);
                    stcgf(&g_h0[nxt][pidx(u, b)], z * h + (1.f - z) * g);
                }
            }
        } else {
            if (tau >= 1) {
                const int bo = (tau + 1) & 1, bn = tau & 1;
                runpass<16, 16>(Wg, 1024, Hsz, gNG8, gT, g_rh1, g_rh1, partG, 16, 32, 0);
                __syncthreads();
                for (int idx = tid; idx < Rg * 32; idx += NTHR) {
                    int row = idx >> 5, b = idx & 31;
                    float acc = bias[BG + row];
#pragma unroll
                    for (int kq = 0; kq < 32; ++kq) acc += partG[(row * 32 + kq) * 32 + b];
                    float g = tanh_(acc);
                    int u = gr_lo + row;
                    float z = ldcgf(&g_z1[pidx(u, b)]);
                    float h = ldcgf(&g_h1[bo][pidx(u, b)]);
                    stcgf(&g_h1[bn][pidx(u, b)], z * h + (1.f - z) * g);
                }
            }
        }
        grid_sync(++bar * NBLK);
    }

    // ---------------- Epilogue ----------------
    if (!l0 && Ry > 0) {
        for (int idx = tid; idx < Ry * 32; idx += NTHR) {
            int row = idx >> 5, b = idx & 31;
            const float* wy = Wy + row * Hsz;
            float acc = bias[BY + row];
            for (int k = 0; k < Hsz; k += 2) {
                unsigned long long sv = ldcg64(&g_h1[0][(k >> 1) * 64 + 2 * b]);
                float2 s = *(float2*)&sv;
                acc = fmaf(wy[k], s.x, fmaf(wy[k + 1], s.y, acc));
            }
            out[(b * Ssz + (Ssz - 1)) * Osz + (y_lo + row)] = acc;
        }
    }
    {
        int i = blockIdx.x * NTHR + tid;
        if (i < Bz * 2 * Hsz) {
            int b = i >> 10, rest = i & 1023;
            float v = (rest < Hsz) ? ldcgf(&g_h0[0][pidx(rest, b)])
                                   : ldcgf(&g_h1[0][pidx(rest - Hsz, b)]);
            out[Bz * Ssz * Osz + i] = v;
        }
    }
}

extern "C" void kernel_launch(void* const* d_in, const int* in_sizes, int n_in,
                              void* d_out, int out_size) {
    cudaFuncSetAttribute(gru_mlp,
                         cudaFuncAttributeMaxDynamicSharedMemorySize, SMEM_BYTES);
    prep_k<<<8192, 1024>>>((const float*)d_in[0]);
    gru_mlp<<<NBLK, NTHR, SMEM_BYTES>>>(
        (const float*)d_in[0], (const float*)d_in[1], (const float*)d_in[2],
        (const float*)d_in[3], (const float*)d_in[4], (const float*)d_in[5],
        (const float*)d_in[6], (const float*)d_in[7], (const float*)d_in[8],
        (const float*)d_in[9], (float*)d_out);
}

// round 9
// speedup vs baseline: 1.4592x; 1.2041x over previous
#include <cuda_runtime.h>

#define NBLK 128
#define NTHR 704
#define NW   22
#define Bz   32
#define Ssz  2048
#define Isz  128
#define Hsz  512
#define Osz  128

// smem float offsets
#define PB_ZR0 32
#define PB_ZR1 5152
#define PB_G0  13344
#define PB_G1  15904
#define PB_Y   20000
#define OFF_W  20512
#define SMEM_FLOATS 40992
#define SMEM_BYTES (SMEM_FLOATS * 4)

// pair-interleaved k-major: idx(k,b) = (k>>1)*64 + 2b + (k&1)
__device__ float g_h0[2][Bz * Hsz];
__device__ float g_h1[2][Bz * Hsz];
__device__ float g_z0[Bz * Hsz];
__device__ float g_rh0[Bz * Hsz];
__device__ float g_z1[Bz * Hsz];
__device__ float g_rh1[Bz * Hsz];
__device__ float g_xT[Ssz * 128 * Bz];
__device__ unsigned g_count;

__device__ __forceinline__ int pidx(int k, int b) {
    return ((k >> 1) << 6) + (b << 1) + (k & 1);
}
__device__ __forceinline__ unsigned long long ldcg64(const float* p) {
    unsigned long long v;
    asm volatile("ld.global.cg.b64 %0, [%1];" : "=l"(v) : "l"(p));
    return v;
}
__device__ __forceinline__ float ldcgf(const float* p) {
    float v;
    asm volatile("ld.global.cg.f32 %0, [%1];" : "=f"(v) : "l"(p));
    return v;
}
__device__ __forceinline__ void stcgf(float* p, float v) {
    asm volatile("st.global.cg.f32 [%0], %1;" :: "l"(p), "f"(v));
}
__device__ __forceinline__ void grid_sync(unsigned target) {
    __syncthreads();
    if (threadIdx.x == 0) {
        asm volatile("red.release.gpu.add.u32 [%0], %1;"
                     :: "l"(&g_count), "r"(1u) : "memory");
        unsigned v;
        do {
            asm volatile("ld.acquire.gpu.u32 %0, [%1];"
                         : "=r"(v) : "l"(&g_count) : "memory");
        } while (v < target);
    }
    __syncthreads();
}
__device__ __forceinline__ float sigmoid_(float x) { return 1.0f / (1.0f + __expf(-x)); }
__device__ __forceinline__ float tanh_(float x)    { return 1.0f - 2.0f / (__expf(2.0f * x) + 1.0f); }
__device__ __forceinline__ unsigned long long f2(unsigned long long w,
                                                 unsigned long long s,
                                                 unsigned long long acc) {
    unsigned long long d;
    asm("fma.rn.f32x2 %0, %1, %2, %3;" : "=l"(d) : "l"(w), "l"(s), "l"(acc));
    return d;
}

// job: ROWS rows x 32 k; state burst (MLP=16) from L2
template <int ROWS>
__device__ __forceinline__ void dot_jobG(const float* __restrict__ wb, int wstride,
                                         const float* __restrict__ sg,
                                         float* __restrict__ pd, int prs) {
    unsigned long long s[16];
#pragma unroll
    for (int p = 0; p < 16; ++p) s[p] = ldcg64(sg + (p << 6));
    unsigned long long acc[ROWS];
#pragma unroll
    for (int r = 0; r < ROWS; ++r) acc[r] = 0ull;
#pragma unroll
    for (int p = 0; p < 16; p += 2) {
#pragma unroll
        for (int r = 0; r < ROWS; ++r) {
            ulonglong2 wv = *(const ulonglong2*)(wb + r * wstride + (p << 1));
            acc[r] = f2(wv.x, s[p], acc[r]);
            acc[r] = f2(wv.y, s[p + 1], acc[r]);
        }
    }
#pragma unroll
    for (int r = 0; r < ROWS; ++r) {
        float2 a = *(float2*)&acc[r];
        pd[r * prs] = a.x + a.y;
    }
}

// one row-group (ROWS rows), KS chunks of 32k; kq<SPLIT reads region A else B
template <int ROWS, int KS, int SPLIT>
__device__ __forceinline__ void runp(const float* __restrict__ W, int wstride,
                                     int coloff, const float* __restrict__ pA,
                                     const float* __restrict__ pB,
                                     float* __restrict__ grp, int rowslots,
                                     int slotoff, int woff) {
    const int lane = threadIdx.x & 31;
    int wid = (threadIdx.x >> 5) - woff;
    if (wid < 0) wid += NW;
    for (int kq = wid; kq < KS; kq += NW) {
        const float* sg = (kq < SPLIT ? pA + kq * 1024
                                      : pB + (kq - SPLIT) * 1024) + 2 * lane;
        const float* wb = W + coloff + (kq << 5);
        float* pd = grp + (slotoff + kq) * 32 + lane;
        dot_jobG<ROWS>(wb, wstride, sg, pd, rowslots * 32);
    }
}

__global__ void prep_k(const float* __restrict__ input) {
    long long idx = (long long)blockIdx.x * 1024 + threadIdx.x;
    if (idx == 0) g_count = 0u;
    if (idx < (long long)Bz * Ssz * Isz) {
        int b = (int)(idx >> 18);
        int rem = (int)(idx & 262143);
        int t = rem >> 7, k = rem & 127;
        g_xT[t * 4096 + pidx(k, b)] = input[idx];
    }
}

extern "C" __global__ void __launch_bounds__(NTHR, 1)
gru_uni(const float* __restrict__ input, const float* __restrict__ h0in,
        const float* __restrict__ Wx0, const float* __restrict__ Wh0,
        const float* __restrict__ bh0, const float* __restrict__ Wx1,
        const float* __restrict__ Wh1, const float* __restrict__ bh1,
        const float* __restrict__ Why, const float* __restrict__ bhy,
        float* __restrict__ out) {
    extern __shared__ float sm[];
    const int tid = threadIdx.x;
    const int bid = blockIdx.x;

    float* bias = sm;                    // [0..24]
    float* pZR0 = sm + PB_ZR0;           // 8 rows x 20 slots
    float* pZR1 = sm + PB_ZR1;           // 8 x 32
    float* pG0  = sm + PB_G0;            // 4 x 20 (x:0-3, h:4-19)
    float* pG1  = sm + PB_G1;            // 4 x 32 (x:0-15, h:16-31)
    float* pY   = sm + PB_Y;             // 1 x 16
    float* Wzr0 = sm + OFF_W;            // 8 x 640
    float* Wg0  = Wzr0 + 5120;           // 4 x 640 (x|h)
    float* Wzr1 = Wg0 + 2560;            // 8 x 1024
    float* Wg1  = Wzr1 + 8192;           // 4 x 1024
    float* Wy   = Wg1 + 4096;            // 1 x 512

    // ---- weights (uniform slices: 8 zr + 4 g per layer, 1 y) ----
    for (int i = tid; i < 8 * 640; i += NTHR) {
        int r = i / 640, k = i - r * 640, j = 8 * bid + r;
        Wzr0[i] = (k < Isz) ? Wx0[j * Isz + k] : Wh0[j * Hsz + k - Isz];
    }
    for (int i = tid; i < 4 * 640; i += NTHR) {
        int r = i / 640, k = i - r * 640, j = 2 * Hsz + 4 * bid + r;
        Wg0[i] = (k < Isz) ? Wx0[j * Isz + k] : Wh0[j * Hsz + k - Isz];
    }
    for (int i = tid; i < 8 * 1024; i += NTHR) {
        int r = i >> 10, k = i & 1023, j = 8 * bid + r;
        Wzr1[i] = (k < Hsz) ? Wx1[j * Hsz + k] : Wh1[j * Hsz + k - Hsz];
    }
    for (int i = tid; i < 4 * 1024; i += NTHR) {
        int r = i >> 10, k = i & 1023, j = 2 * Hsz + 4 * bid + r;
        Wg1[i] = (k < Hsz) ? Wx1[j * Hsz + k] : Wh1[j * Hsz + k - Hsz];
    }
    for (int i = tid; i < Hsz; i += NTHR) Wy[i] = Why[bid * Hsz + i];
    if (tid < 8)       bias[tid] = bh0[8 * bid + tid];
    else if (tid < 12) bias[tid] = bh0[2 * Hsz + 4 * bid + tid - 8];
    else if (tid < 20) bias[tid] = bh1[8 * bid + tid - 12];
    else if (tid < 24) bias[tid] = bh1[2 * Hsz + 4 * bid + tid - 20];
    else if (tid == 24) bias[tid] = bhy[bid];

    // ---- init state ----
    {
        int i = bid * NTHR + tid;
        if (i < Bz * 2 * Hsz) {
            int b = i >> 10, rest = i & 1023;
            float v = h0in[i];
            if (rest < Hsz) stcgf(&g_h0[0][pidx(rest, b)], v);
            else            stcgf(&g_h1[0][pidx(rest - Hsz, b)], v);
        }
    }
    unsigned bar = 0;
    grid_sync(++bar * NBLK);

    for (int tau = 0; tau <= Ssz; ++tau) {
        const int par = tau & 1;            // h0_old buffer (L0 step tau)
        const int bo = tau & 1;             // h0' buffer (L1 step tau-1 input)
        const int bn = (tau + 1) & 1;       // h1_old buffer
        const float* xT = g_xT + tau * 4096;
        const float* h0o = g_h0[par];
        const float* h0n = g_h0[bo];
        const float* h1o = g_h1[bn];

        // ================= PHASE 1 =================
        if (tau < Ssz) {
            runp<8, 20, 4>(Wzr0, 640, 0, xT, h0o, pZR0, 20, 0, 0);
            runp<4, 4, 4>(Wg0, 640, 0, xT, xT, pG0, 20, 0, 20);
        }
        if (tau >= 1) {
            runp<8, 32, 16>(Wzr1, 1024, 0, h0n, h1o, pZR1, 32, 0, 2);
            runp<4, 16, 16>(Wg1, 1024, 0, h0n, h0n, pG1, 32, 0, 18);
        }
        if (tau >= 2) runp<1, 16, 16>(Wy, 512, 0, h1o, h1o, pY, 16, 0, 2);
        __syncthreads();
        for (int idx = tid; idx < 544; idx += NTHR) {
            int row = idx >> 5, b = idx & 31;
            if (row < 8) {
                if (tau < Ssz) {
                    float acc = bias[row];
#pragma unroll
                    for (int kq = 0; kq < 20; ++kq) acc += pZR0[(row * 20 + kq) * 32 + b];
                    float s = sigmoid_(acc);
                    int j = 8 * bid + row;
                    if (j < Hsz) stcgf(&g_z0[pidx(j, b)], s);
                    else stcgf(&g_rh0[pidx(j - Hsz, b)],
                               s * ldcgf(&g_h0[par][pidx(j - Hsz, b)]));
                }
            } else if (row < 16) {
                if (tau >= 1) {
                    int r2 = row - 8;
                    float acc = bias[12 + r2];
#pragma unroll
                    for (int kq = 0; kq < 32; ++kq) acc += pZR1[(r2 * 32 + kq) * 32 + b];
                    float s = sigmoid_(acc);
                    int j = 8 * bid + r2;
                    if (j < Hsz) stcgf(&g_z1[pidx(j, b)], s);
                    else stcgf(&g_rh1[pidx(j - Hsz, b)],
                               s * ldcgf(&g_h1[bn][pidx(j - Hsz, b)]));
                }
            } else {
                if (tau >= 2) {
                    float acc = bias[24];
#pragma unroll
                    for (int kq = 0; kq < 16; ++kq) acc += pY[kq * 32 + b];
                    out[(b * Ssz + (tau - 2)) * Osz + bid] = acc;
                }
            }
        }
        grid_sync(++bar * NBLK);

        // ================= PHASE 2 =================
        if (tau < Ssz) runp<4, 16, 16>(Wg0, 640, Isz, g_rh0, g_rh0, pG0, 20, 4, 0);
        if (tau >= 1)  runp<4, 16, 16>(Wg1, 1024, Hsz, g_rh1, g_rh1, pG1, 32, 16, 16);
        __syncthreads();
        for (int idx = tid; idx < 256; idx += NTHR) {
            int row = idx >> 5, b = idx & 31;
            if (row < 4) {
                if (tau < Ssz) {
                    float acc = bias[8 + row];
#pragma unroll
                    for (int kq = 0; kq < 20; ++kq) acc += pG0[(row * 20 + kq) * 32 + b];
                    float g = tanh_(acc);
                    int u = 4 * bid + row;
                    float z = ldcgf(&g_z0[pidx(u, b)]);
                    float h = ldcgf(&g_h0[par][pidx(u, b)]);
                    stcgf(&g_h0[par ^ 1][pidx(u, b)], z * h + (1.f - z) * g);
                }
            } else {
                if (tau >= 1) {
                    int r2 = row - 4;
                    float acc = bias[20 + r2];
#pragma unroll
                    for (int kq = 0; kq < 32; ++kq) acc += pG1[(r2 * 32 + kq) * 32 + b];
                    float g = tanh_(acc);
                    int u = 4 * bid + r2;
                    float z = ldcgf(&g_z1[pidx(u, b)]);
                    float h = ldcgf(&g_h1[bn][pidx(u, b)]);
                    stcgf(&g_h1[tau & 1][pidx(u, b)], z * h + (1.f - z) * g);
                }
            }
        }
        grid_sync(++bar * NBLK);
    }

    // ---------------- Epilogue ----------------
    {   // y(S-1) from final h1 (buffer 0): one row per block
        for (int idx = tid; idx < 32; idx += NTHR) { }
        if (tid < 32) {
            int b = tid;
            float acc = bias[24];
            for (int k = 0; k < Hsz; k += 2) {
                unsigned long long sv = ldcg64(&g_h1[0][(k >> 1) * 64 + 2 * b]);
                float2 s = *(float2*)&sv;
                acc = fmaf(Wy[k], s.x, fmaf(Wy[k + 1], s.y, acc));
            }
            out[(b * Ssz + (Ssz - 1)) * Osz + bid] = acc;
        }
    }
    {
        int i = bid * NTHR + tid;
        if (i < Bz * 2 * Hsz) {
            int b = i >> 10, rest = i & 1023;
            float v = (rest < Hsz) ? ldcgf(&g_h0[0][pidx(rest, b)])
                                   : ldcgf(&g_h1[0][pidx(rest - Hsz, b)]);
            out[Bz * Ssz * Osz + i] = v;
        }
    }
}

extern "C" void kernel_launch(void* const* d_in, const int* in_sizes, int n_in,
                              void* d_out, int out_size) {
    cudaFuncSetAttribute(gru_uni,
                         cudaFuncAttributeMaxDynamicSharedMemorySize, SMEM_BYTES);
    prep_k<<<8192, 1024>>>((const float*)d_in[0]);
    gru_uni<<<NBLK, NTHR, SMEM_BYTES>>>(
        (const float*)d_in[0], (const float*)d_in[1], (const float*)d_in[2],
        (const float*)d_in[3], (const float*)d_in[4], (const float*)d_in[5],
        (const float*)d_in[6], (const float*)d_in[7], (const float*)d_in[8],
        (const float*)d_in[9], (float*)d_out);
}

// round 10
// speedup vs baseline: 1.5475x; 1.0605x over previous
#include <cuda_runtime.h>

#define NBLK 128
#define NTHR 704
#define NW   22
#define Bz   32
#define Ssz  2048
#define Isz  128
#define Hsz  512
#define Osz  128

#define PB_ZR0 32
#define PB_ZR1 5152
#define PB_G0  13344
#define PB_G1  15904
#define PB_Y   20000
#define OFF_W  20512
#define SMEM_FLOATS 40992
#define SMEM_BYTES (SMEM_FLOATS * 4)

// pair-interleaved k-major: idx(k,b) = (k>>1)*64 + 2b + (k&1)
__device__ float g_h0[2][Bz * Hsz];
__device__ float g_h1[2][Bz * Hsz];
__device__ float g_z0[Bz * Hsz];
__device__ float g_rh0[Bz * Hsz];
__device__ float g_z1[Bz * Hsz];
__device__ float g_rh1[Bz * Hsz];
__device__ float g_xT[Ssz * 128 * Bz];
__device__ unsigned g_count;

__device__ __forceinline__ int pidx(int k, int b) {
    return ((k >> 1) << 6) + (b << 1) + (k & 1);
}
__device__ __forceinline__ unsigned long long ldcg64(const float* p) {
    unsigned long long v;
    asm volatile("ld.global.cg.b64 %0, [%1];" : "=l"(v) : "l"(p));
    return v;
}
__device__ __forceinline__ float ldcgf(const float* p) {
    float v;
    asm volatile("ld.global.cg.f32 %0, [%1];" : "=f"(v) : "l"(p));
    return v;
}
__device__ __forceinline__ void stcgf(float* p, float v) {
    asm volatile("st.global.cg.f32 [%0], %1;" :: "l"(p), "f"(v));
}
__device__ __forceinline__ void grid_sync(unsigned target) {
    __syncthreads();
    if (threadIdx.x == 0) {
        asm volatile("red.release.gpu.add.u32 [%0], %1;"
                     :: "l"(&g_count), "r"(1u) : "memory");
        unsigned v;
        do {
            asm volatile("ld.acquire.gpu.u32 %0, [%1];"
                         : "=r"(v) : "l"(&g_count) : "memory");
        } while (v < target);
    }
    __syncthreads();
}
__device__ __forceinline__ float sigmoid_(float x) { return 1.0f / (1.0f + __expf(-x)); }
__device__ __forceinline__ float tanh_(float x)    { return 1.0f - 2.0f / (__expf(2.0f * x) + 1.0f); }
__device__ __forceinline__ unsigned long long f2(unsigned long long w,
                                                 unsigned long long s,
                                                 unsigned long long acc) {
    unsigned long long d;
    asm("fma.rn.f32x2 %0, %1, %2, %3;" : "=l"(d) : "l"(w), "l"(s), "l"(acc));
    return d;
}

// merged job: R1 rows from wb1 + R2 rows from wb2, one 32k state chunk (MLP=16)
template <int R1, int R2>
__device__ __forceinline__ void dotm(const float* __restrict__ wb1, int ws1,
                                     const float* __restrict__ wb2, int ws2,
                                     const float* __restrict__ sg,
                                     float* __restrict__ pd1, int prs1,
                                     float* __restrict__ pd2, int prs2) {
    unsigned long long s[16];
#pragma unroll
    for (int p = 0; p < 16; ++p) s[p] = ldcg64(sg + (p << 6));
    unsigned long long acc[R1 + R2];
#pragma unroll
    for (int i = 0; i < R1 + R2; ++i) acc[i] = 0ull;
#pragma unroll
    for (int p = 0; p < 16; p += 2) {
#pragma unroll
        for (int r = 0; r < R1; ++r) {
            ulonglong2 wv = *(const ulonglong2*)(wb1 + r * ws1 + (p << 1));
            acc[r] = f2(wv.x, s[p], acc[r]);
            acc[r] = f2(wv.y, s[p + 1], acc[r]);
        }
#pragma unroll
        for (int r = 0; r < R2; ++r) {
            ulonglong2 wv = *(const ulonglong2*)(wb2 + r * ws2 + (p << 1));
            acc[R1 + r] = f2(wv.x, s[p], acc[R1 + r]);
            acc[R1 + r] = f2(wv.y, s[p + 1], acc[R1 + r]);
        }
    }
#pragma unroll
    for (int r = 0; r < R1; ++r) { float2 a = *(float2*)&acc[r]; pd1[r * prs1] = a.x + a.y; }
#pragma unroll
    for (int r = 0; r < R2; ++r) { float2 a = *(float2*)&acc[R1 + r]; pd2[r * prs2] = a.x + a.y; }
}

__global__ void prep_k(const float* __restrict__ input) {
    long long idx = (long long)blockIdx.x * 1024 + threadIdx.x;
    if (idx == 0) g_count = 0u;
    if (idx < (long long)Bz * Ssz * Isz) {
        int b = (int)(idx >> 18);
        int rem = (int)(idx & 262143);
        int t = rem >> 7, k = rem & 127;
        g_xT[t * 4096 + pidx(k, b)] = input[idx];
    }
}

extern "C" __global__ void __launch_bounds__(NTHR, 1)
gru_m(const float* __restrict__ input, const float* __restrict__ h0in,
      const float* __restrict__ Wx0, const float* __restrict__ Wh0,
      const float* __restrict__ bh0, const float* __restrict__ Wx1,
      const float* __restrict__ Wh1, const float* __restrict__ bh1,
      const float* __restrict__ Why, const float* __restrict__ bhy,
      float* __restrict__ out) {
    extern __shared__ float sm[];
    const int tid = threadIdx.x;
    const int bid = blockIdx.x;
    const int wid = tid >> 5, lane = tid & 31;

    float* bias = sm;
    float* pZR0 = sm + PB_ZR0;           // 8 x 20 slots
    float* pZR1 = sm + PB_ZR1;           // 8 x 32
    float* pG0  = sm + PB_G0;            // 4 x 20 (x:0-3, h:4-19)
    float* pG1  = sm + PB_G1;            // 4 x 32 (x:0-15, h:16-31)
    float* pY   = sm + PB_Y;             // 1 x 16
    float* Wzr0 = sm + OFF_W;            // 8 x 640
    float* Wg0  = Wzr0 + 5120;           // 4 x 640
    float* Wzr1 = Wg0 + 2560;            // 8 x 1024
    float* Wg1  = Wzr1 + 8192;           // 4 x 1024
    float* Wy   = Wg1 + 4096;            // 1 x 512

    for (int i = tid; i < 8 * 640; i += NTHR) {
        int r = i / 640, k = i - r * 640, j = 8 * bid + r;
        Wzr0[i] = (k < Isz) ? Wx0[j * Isz + k] : Wh0[j * Hsz + k - Isz];
    }
    for (int i = tid; i < 4 * 640; i += NTHR) {
        int r = i / 640, k = i - r * 640, j = 2 * Hsz + 4 * bid + r;
        Wg0[i] = (k < Isz) ? Wx0[j * Isz + k] : Wh0[j * Hsz + k - Isz];
    }
    for (int i = tid; i < 8 * 1024; i += NTHR) {
        int r = i >> 10, k = i & 1023, j = 8 * bid + r;
        Wzr1[i] = (k < Hsz) ? Wx1[j * Hsz + k] : Wh1[j * Hsz + k - Hsz];
    }
    for (int i = tid; i < 4 * 1024; i += NTHR) {
        int r = i >> 10, k = i & 1023, j = 2 * Hsz + 4 * bid + r;
        Wg1[i] = (k < Hsz) ? Wx1[j * Hsz + k] : Wh1[j * Hsz + k - Hsz];
    }
    for (int i = tid; i < Hsz; i += NTHR) Wy[i] = Why[bid * Hsz + i];
    if (tid < 8)       bias[tid] = bh0[8 * bid + tid];
    else if (tid < 12) bias[tid] = bh0[2 * Hsz + 4 * bid + tid - 8];
    else if (tid < 20) bias[tid] = bh1[8 * bid + tid - 12];
    else if (tid < 24) bias[tid] = bh1[2 * Hsz + 4 * bid + tid - 20];
    else if (tid == 24) bias[tid] = bhy[bid];

    {
        int i = bid * NTHR + tid;
        if (i < Bz * 2 * Hsz) {
            int b = i >> 10, rest = i & 1023;
            float v = h0in[i];
            if (rest < Hsz) stcgf(&g_h0[0][pidx(rest, b)], v);
            else            stcgf(&g_h1[0][pidx(rest - Hsz, b)], v);
        }
    }
    unsigned bar = 0;
    grid_sync(++bar * NBLK);

    for (int tau = 0; tau <= Ssz; ++tau) {
        const int par = tau & 1;
        const int bn = (tau + 1) & 1;
        const float* xT = g_xT + (long long)tau * 4096;
        const float* h0o = g_h0[par];
        const float* h0n = g_h0[par];        // h0' written this iter into par^1? no:
        // NOTE: phase2 of iter tau-1 wrote h0 into buffer (tau-1&1)^1 = tau&1 = par.
        // So h0n (h0' for L1) IS g_h0[par]... but h0_old for L0 (this iter) is ALSO
        // buffer par?? Keep R9 semantics exactly: h0o = g_h0[par] (L0 old),
        // h0n = g_h0[bo] with bo = tau&1 -> same buffer par. (R9 used bo = tau&1.)
        const float* h1o = g_h1[bn];

        // ================= PHASE 1 =================
        // schedule: w0,w1: XA pairs; w2-9: B pairs; w10-13: C pairs;
        //           w14-21: one C + XB pair
        if (wid < 2) {
            if (tau < Ssz) {
#pragma unroll
                for (int j = 0; j < 2; ++j) {
                    int kq = 2 * wid + j;
                    dotm<8, 4>(Wzr0 + kq * 32, 640, Wg0 + kq * 32, 640,
                               xT + kq * 1024 + 2 * lane,
                               pZR0 + kq * 32 + lane, 640,
                               pG0 + kq * 32 + lane, 640);
                }
            }
        } else if (wid < 10) {
            if (tau >= 1) {
#pragma unroll
                for (int j = 0; j < 2; ++j) {
                    int kq = 2 * (wid - 2) + j;
                    dotm<8, 4>(Wzr1 + kq * 32, 1024, Wg1 + kq * 32, 1024,
                               h0n + kq * 1024 + 2 * lane,
                               pZR1 + kq * 32 + lane, 1024,
                               pG1 + kq * 32 + lane, 1024);
                }
            }
        } else if (wid < 14) {
            if (tau >= 1) {
#pragma unroll
                for (int j = 0; j < 2; ++j) {
                    int kq = 2 * (wid - 10) + j;
                    dotm<8, 1>(Wzr1 + (16 + kq) * 32, 1024, Wy + kq * 32, 512,
                               h1o + kq * 1024 + 2 * lane,
                               pZR1 + (16 + kq) * 32 + lane, 1024,
                               pY + kq * 32 + lane, 1);
                }
            }
        } else {
            if (tau >= 1) {
                int kq = 8 + (wid - 14);
                dotm<8, 1>(Wzr1 + (16 + kq) * 32, 1024, Wy + kq * 32, 512,
                           h1o + kq * 1024 + 2 * lane,
                           pZR1 + (16 + kq) * 32 + lane, 1024,
                           pY + kq * 32 + lane, 1);
            }
            if (tau < Ssz) {
#pragma unroll
                for (int j = 0; j < 2; ++j) {
                    int kq = 2 * (wid - 14) + j;
                    dotm<8, 0>(Wzr0 + (4 + kq) * 32, 640, Wzr0, 0,
                               h0o + kq * 1024 + 2 * lane,
                               pZR0 + (4 + kq) * 32 + lane, 640,
                               pZR0, 1);
                }
            }
        }
        __syncthreads();
        for (int idx = tid; idx < 544; idx += NTHR) {
            int row = idx >> 5, b = idx & 31;
            if (row < 8) {
                if (tau < Ssz) {
                    float acc = bias[row];
#pragma unroll
                    for (int kq = 0; kq < 20; ++kq) acc += pZR0[(row * 20 + kq) * 32 + b];
                    float s = sigmoid_(acc);
                    int j = 8 * bid + row;
                    if (j < Hsz) stcgf(&g_z0[pidx(j, b)], s);
                    else stcgf(&g_rh0[pidx(j - Hsz, b)],
                               s * ldcgf(&g_h0[par][pidx(j - Hsz, b)]));
                }
            } else if (row < 16) {
                if (tau >= 1) {
                    int r2 = row - 8;
                    float acc = bias[12 + r2];
#pragma unroll
                    for (int kq = 0; kq < 32; ++kq) acc += pZR1[(r2 * 32 + kq) * 32 + b];
                    float s = sigmoid_(acc);
                    int j = 8 * bid + r2;
                    if (j < Hsz) stcgf(&g_z1[pidx(j, b)], s);
                    else stcgf(&g_rh1[pidx(j - Hsz, b)],
                               s * ldcgf(&g_h1[bn][pidx(j - Hsz, b)]));
                }
            } else {
                if (tau >= 2) {
                    float acc = bias[24];
#pragma unroll
                    for (int kq = 0; kq < 16; ++kq) acc += pY[kq * 32 + b];
                    out[(b * Ssz + (tau - 2)) * Osz + bid] = acc;
                }
            }
        }
        grid_sync(++bar * NBLK);

        // ================= PHASE 2 =================
        if (wid < 16 && tau < Ssz) {
            int kq = wid;
            dotm<4, 0>(Wg0 + (4 + kq) * 32, 640, Wg0, 0,
                       g_rh0 + kq * 1024 + 2 * lane,
                       pG0 + (4 + kq) * 32 + lane, 640, pG0, 1);
        }
        {
            int g1w = wid - 16; if (g1w < 0) g1w += NW;
            if (g1w < 16 && tau >= 1) {
                int kq = g1w;
                dotm<4, 0>(Wg1 + (16 + kq) * 32, 1024, Wg1, 0,
                           g_rh1 + kq * 1024 + 2 * lane,
                           pG1 + (16 + kq) * 32 + lane, 1024, pG1, 1);
            }
        }
        __syncthreads();
        for (int idx = tid; idx < 256; idx += NTHR) {
            int row = idx >> 5, b = idx & 31;
            if (row < 4) {
                if (tau < Ssz) {
                    float acc = bias[8 + row];
#pragma unroll
                    for (int kq = 0; kq < 20; ++kq) acc += pG0[(row * 20 + kq) * 32 + b];
                    float g = tanh_(acc);
                    int u = 4 * bid + row;
                    float z = ldcgf(&g_z0[pidx(u, b)]);
                    float h = ldcgf(&g_h0[par][pidx(u, b)]);
                    stcgf(&g_h0[par ^ 1][pidx(u, b)], z * h + (1.f - z) * g);
                }
            } else {
                if (tau >= 1) {
                    int r2 = row - 4;
                    float acc = bias[20 + r2];
#pragma unroll
                    for (int kq = 0; kq < 32; ++kq) acc += pG1[(r2 * 32 + kq) * 32 + b];
                    float g = tanh_(acc);
                    int u = 4 * bid + r2;
                    float z = ldcgf(&g_z1[pidx(u, b)]);
                    float h = ldcgf(&g_h1[bn][pidx(u, b)]);
                    stcgf(&g_h1[tau & 1][pidx(u, b)], z * h + (1.f - z) * g);
                }
            }
        }
        grid_sync(++bar * NBLK);
    }

    // ---------------- Epilogue ----------------
    if (tid < 32) {
        int b = tid;
        float acc = bias[24];
        for (int k = 0; k < Hsz; k += 2) {
            unsigned long long sv = ldcg64(&g_h1[0][(k >> 1) * 64 + 2 * b]);
            float2 s = *(float2*)&sv;
            acc = fmaf(Wy[k], s.x, fmaf(Wy[k + 1], s.y, acc));
        }
        out[(b * Ssz + (Ssz - 1)) * Osz + bid] = acc;
    }
    {
        int i = bid * NTHR + tid;
        if (i < Bz * 2 * Hsz) {
            int b = i >> 10, rest = i & 1023;
            float v = (rest < Hsz) ? ldcgf(&g_h0[0][pidx(rest, b)])
                                   : ldcgf(&g_h1[0][pidx(rest - Hsz, b)]);
            out[Bz * Ssz * Osz + i] = v;
        }
    }
}

extern "C" void kernel_launch(void* const* d_in, const int* in_sizes, int n_in,
                              void* d_out, int out_size) {
    cudaFuncSetAttribute(gru_m,
                         cudaFuncAttributeMaxDynamicSharedMemorySize, SMEM_BYTES);
    prep_k<<<8192, 1024>>>((const float*)d_in[0]);
    gru_m<<<NBLK, NTHR, SMEM_BYTES>>>(
        (const float*)d_in[0], (const float*)d_in[1], (const float*)d_in[2],
        (const float*)d_in[3], (const float*)d_in[4], (const float*)d_in[5],
        (const float*)d_in[6], (const float*)d_in[7], (const float*)d_in[8],
        (const float*)d_in[9], (float*)d_out);
}

// round 11
// speedup vs baseline: 1.5894x; 1.0271x over previous
#include <cuda_runtime.h>

#define NBLK 128
#define NTHR 768
#define Bz   32
#define Ssz  2048
#define Isz  128
#define Hsz  512
#define Osz  128

#define PB_ZR0 32
#define PB_ZR1 5152
#define PB_G0  13344
#define PB_G1  15904
#define PB_Y   20000
#define OFF_W  20512
#define SMEM_FLOATS 40992
#define SMEM_BYTES (SMEM_FLOATS * 4)

// quad-interleaved k-major: idx(k,b) = (k>>2)*128 + 4b + (k&3)
__device__ float g_h0[2][Bz * Hsz];
__device__ float g_h1[2][Bz * Hsz];
__device__ float g_z0[Bz * Hsz];
__device__ float g_rh0[Bz * Hsz];
__device__ float g_z1[Bz * Hsz];
__device__ float g_rh1[Bz * Hsz];
__device__ float g_xT[(long long)Ssz * 128 * Bz];
__device__ unsigned g_count;

__device__ __forceinline__ int pidx(int k, int b) {
    return ((k >> 2) << 7) + (b << 2) + (k & 3);
}
__device__ __forceinline__ float4 ldcg128(const float* p) {
    float4 v;
    asm volatile("ld.global.cg.v4.f32 {%0,%1,%2,%3}, [%4];"
                 : "=f"(v.x), "=f"(v.y), "=f"(v.z), "=f"(v.w) : "l"(p));
    return v;
}
__device__ __forceinline__ float ldcgf(const float* p) {
    float v;
    asm volatile("ld.global.cg.f32 %0, [%1];" : "=f"(v) : "l"(p));
    return v;
}
__device__ __forceinline__ void stcgf(float* p, float v) {
    asm volatile("st.global.cg.f32 [%0], %1;" :: "l"(p), "f"(v));
}
__device__ __forceinline__ void bar_arrive() {
    __syncthreads();
    if (threadIdx.x == 0)
        asm volatile("red.release.gpu.add.u32 [%0], %1;"
                     :: "l"(&g_count), "r"(1u) : "memory");
}
__device__ __forceinline__ void bar_wait(unsigned target) {
    if (threadIdx.x == 0) {
        unsigned v;
        do {
            asm volatile("ld.acquire.gpu.u32 %0, [%1];"
                         : "=r"(v) : "l"(&g_count) : "memory");
        } while (v < target);
    }
    __syncthreads();
}
__device__ __forceinline__ float sigmoid_(float x) { return 1.0f / (1.0f + __expf(-x)); }
__device__ __forceinline__ float tanh_(float x)    { return 1.0f - 2.0f / (__expf(2.0f * x) + 1.0f); }
__device__ __forceinline__ unsigned long long f2(unsigned long long w,
                                                 unsigned long long s,
                                                 unsigned long long acc) {
    unsigned long long d;
    asm("fma.rn.f32x2 %0, %1, %2, %3;" : "=l"(d) : "l"(w), "l"(s), "l"(acc));
    return d;
}

// merged job: R1 rows (wb1) + R2 rows (wb2) x one 32k chunk; 8x LDG.128 burst
template <int R1, int R2>
__device__ __forceinline__ void dotm(const float* __restrict__ wb1, int ws1,
                                     const float* __restrict__ wb2, int ws2,
                                     const float* __restrict__ sg,
                                     float* __restrict__ pd1, int prs1,
                                     float* __restrict__ pd2, int prs2) {
    float4 s4[8];
#pragma unroll
    for (int p = 0; p < 8; ++p) s4[p] = ldcg128(sg + (p << 7));
    unsigned long long acc[R1 + R2];
#pragma unroll
    for (int i = 0; i < R1 + R2; ++i) acc[i] = 0ull;
#pragma unroll
    for (int p = 0; p < 8; ++p) {
        ulonglong2 sv = *(ulonglong2*)&s4[p];
#pragma unroll
        for (int r = 0; r < R1; ++r) {
            ulonglong2 wv = *(const ulonglong2*)(wb1 + r * ws1 + (p << 2));
            acc[r] = f2(wv.x, sv.x, acc[r]);
            acc[r] = f2(wv.y, sv.y, acc[r]);
        }
#pragma unroll
        for (int r = 0; r < R2; ++r) {
            ulonglong2 wv = *(const ulonglong2*)(wb2 + r * ws2 + (p << 2));
            acc[R1 + r] = f2(wv.x, sv.x, acc[R1 + r]);
            acc[R1 + r] = f2(wv.y, sv.y, acc[R1 + r]);
        }
    }
#pragma unroll
    for (int r = 0; r < R1; ++r) { float2 a = *(float2*)&acc[r]; pd1[r * prs1] = a.x + a.y; }
#pragma unroll
    for (int r = 0; r < R2; ++r) { float2 a = *(float2*)&acc[R1 + r]; pd2[r * prs2] = a.x + a.y; }
}

__global__ void prep_k(const float* __restrict__ input) {
    long long idx = (long long)blockIdx.x * 1024 + threadIdx.x;
    if (idx == 0) g_count = 0u;
    if (idx < (long long)Bz * Ssz * Isz) {
        int b = (int)(idx >> 18);
        int rem = (int)(idx & 262143);
        int t = rem >> 7, k = rem & 127;
        g_xT[(long long)t * 4096 + pidx(k, b)] = input[idx];
    }
}

extern "C" __global__ void __launch_bounds__(NTHR, 1)
gru_q(const float* __restrict__ input, const float* __restrict__ h0in,
      const float* __restrict__ Wx0, const float* __restrict__ Wh0,
      const float* __restrict__ bh0, const float* __restrict__ Wx1,
      const float* __restrict__ Wh1, const float* __restrict__ bh1,
      const float* __restrict__ Why, const float* __restrict__ bhy,
      float* __restrict__ out) {
    extern __shared__ float sm[];
    const int tid = threadIdx.x;
    const int bid = blockIdx.x;
    const int wid = tid >> 5, lane = tid & 31;

    float* bias = sm;
    float* pZR0 = sm + PB_ZR0;           // 8 x 20 (x:0-3 gap, h:4-19)
    float* pZR1 = sm + PB_ZR1;           // 8 x 32 (h0:0-15, h1:16-31)
    float* pG0  = sm + PB_G0;            // 4 x 20 (x:0-3 gap, h:4-19)
    float* pG1  = sm + PB_G1;            // 4 x 32 (x:0-15, h:16-31)
    float* pY   = sm + PB_Y;             // 1 x 16
    float* Wzr0 = sm + OFF_W;            // 8 x 640
    float* Wg0  = Wzr0 + 5120;           // 4 x 640
    float* Wzr1 = Wg0 + 2560;            // 8 x 1024
    float* Wg1  = Wzr1 + 8192;           // 4 x 1024
    float* Wy   = Wg1 + 4096;            // 1 x 512

    for (int i = tid; i < 8 * 640; i += NTHR) {
        int r = i / 640, k = i - r * 640, j = 8 * bid + r;
        Wzr0[i] = (k < Isz) ? Wx0[j * Isz + k] : Wh0[j * Hsz + k - Isz];
    }
    for (int i = tid; i < 4 * 640; i += NTHR) {
        int r = i / 640, k = i - r * 640, j = 2 * Hsz + 4 * bid + r;
        Wg0[i] = (k < Isz) ? Wx0[j * Isz + k] : Wh0[j * Hsz + k - Isz];
    }
    for (int i = tid; i < 8 * 1024; i += NTHR) {
        int r = i >> 10, k = i & 1023, j = 8 * bid + r;
        Wzr1[i] = (k < Hsz) ? Wx1[j * Hsz + k] : Wh1[j * Hsz + k - Hsz];
    }
    for (int i = tid; i < 4 * 1024; i += NTHR) {
        int r = i >> 10, k = i & 1023, j = 2 * Hsz + 4 * bid + r;
        Wg1[i] = (k < Hsz) ? Wx1[j * Hsz + k] : Wh1[j * Hsz + k - Hsz];
    }
    for (int i = tid; i < Hsz; i += NTHR) Wy[i] = Why[bid * Hsz + i];
    if (tid < 8)       bias[tid] = bh0[8 * bid + tid];
    else if (tid < 12) bias[tid] = bh0[2 * Hsz + 4 * bid + tid - 8];
    else if (tid < 20) bias[tid] = bh1[8 * bid + tid - 12];
    else if (tid < 24) bias[tid] = bh1[2 * Hsz + 4 * bid + tid - 20];
    else if (tid == 24) bias[tid] = bhy[bid];

    {
        int i = bid * NTHR + tid;
        if (i < Bz * 2 * Hsz) {
            int b = i >> 10, rest = i & 1023;
            float v = h0in[i];
            if (rest < Hsz) stcgf(&g_h0[0][pidx(rest, b)], v);
            else            stcgf(&g_h1[0][pidx(rest - Hsz, b)], v);
        }
    }
    __syncthreads();
    // gap-equivalent for tau=0: x dots of step 0
    if (wid < 4) {
        int kq = wid;
        dotm<8, 4>(Wzr0 + kq * 32, 640, Wg0 + kq * 32, 640,
                   g_xT + kq * 1024 + 4 * lane,
                   pZR0 + kq * 32 + lane, 640,
                   pG0 + kq * 32 + lane, 640);
    }
    unsigned bar = 0;
    bar_arrive(); bar_wait(++bar * NBLK);

    for (int tau = 0; tau <= Ssz; ++tau) {
        const int par = tau & 1;            // h0 buffer: L0 old == L1 input (wavefront)
        const int bn = (tau + 1) & 1;       // h1_old buffer
        const float* h0c = g_h0[par];
        const float* h1o = g_h1[bn];

        // ================= PHASE 1 =================
        if (wid < 16) {
            if (tau >= 1) {
                int kq = wid;
                // zr1 (8r) + g1-x (4r) on h0 chunk kq
                dotm<8, 4>(Wzr1 + kq * 32, 1024, Wg1 + kq * 32, 1024,
                           h0c + kq * 1024 + 4 * lane,
                           pZR1 + kq * 32 + lane, 1024,
                           pG1 + kq * 32 + lane, 1024);
                // zr1-h (8r) + y (1r) on h1_old chunk kq
                dotm<8, 1>(Wzr1 + 512 + kq * 32, 1024, Wy + kq * 32, 512,
                           h1o + kq * 1024 + 4 * lane,
                           pZR1 + (16 + kq) * 32 + lane, 1024,
                           pY + kq * 32 + lane, 1);
            }
        } else {
            if (tau < Ssz) {
#pragma unroll
                for (int j = 0; j < 2; ++j) {
                    int kq = 2 * (wid - 16) + j;
                    // zr0-h (8r) on h0 chunk kq
                    dotm<8, 0>(Wzr0 + Isz + kq * 32, 640, Wzr0, 640,
                               h0c + kq * 1024 + 4 * lane,
                               pZR0 + (4 + kq) * 32 + lane, 640,
                               pZR0 + lane, 640);
                }
            }
        }
        __syncthreads();
        if (tid < 544) {
            int row = tid >> 5, b = tid & 31;
            if (row < 8) {
                if (tau < Ssz) {
                    float acc = bias[row];
#pragma unroll
                    for (int kq = 0; kq < 20; ++kq) acc += pZR0[(row * 20 + kq) * 32 + b];
                    float s = sigmoid_(acc);
                    int j = 8 * bid + row;
                    if (j < Hsz) stcgf(&g_z0[pidx(j, b)], s);
                    else stcgf(&g_rh0[pidx(j - Hsz, b)],
                               s * ldcgf(&g_h0[par][pidx(j - Hsz, b)]));
                }
            } else if (row < 16) {
                if (tau >= 1) {
                    int r2 = row - 8;
                    float acc = bias[12 + r2];
#pragma unroll
                    for (int kq = 0; kq < 32; ++kq) acc += pZR1[(r2 * 32 + kq) * 32 + b];
                    float s = sigmoid_(acc);
                    int j = 8 * bid + r2;
                    if (j < Hsz) stcgf(&g_z1[pidx(j, b)], s);
                    else stcgf(&g_rh1[pidx(j - Hsz, b)],
                               s * ldcgf(&g_h1[bn][pidx(j - Hsz, b)]));
                }
            } else {
                if (tau >= 2) {
                    float acc = bias[24];
#pragma unroll
                    for (int kq = 0; kq < 16; ++kq) acc += pY[kq * 32 + b];
                    out[(b * Ssz + (tau - 2)) * Osz + bid] = acc;
                }
            }
        }
        bar_arrive(); bar_wait(++bar * NBLK);

        // ================= PHASE 2 =================
        if (wid < 16) {
            if (tau >= 1) {
                int kq = wid;   // g1-h (4r) on rh1 chunk kq
                dotm<4, 0>(Wg1 + 512 + kq * 32, 1024, Wg1, 1024,
                           g_rh1 + kq * 1024 + 4 * lane,
                           pG1 + (16 + kq) * 32 + lane, 1024,
                           pG1 + lane, 1024);
            }
        } else {
            if (tau < Ssz) {
#pragma unroll
                for (int j = 0; j < 2; ++j) {
                    int kq = 2 * (wid - 16) + j;   // g0-h (4r) on rh0 chunk kq
                    dotm<4, 0>(Wg0 + Isz + kq * 32, 640, Wg0, 640,
                               g_rh0 + kq * 1024 + 4 * lane,
                               pG0 + (4 + kq) * 32 + lane, 640,
                               pG0 + lane, 640);
                }
            }
        }
        __syncthreads();
        if (tid < 256) {
            int row = tid >> 5, b = tid & 31;
            if (row < 4) {
                if (tau < Ssz) {
                    float acc = bias[8 + row];
#pragma unroll
                    for (int kq = 0; kq < 20; ++kq) acc += pG0[(row * 20 + kq) * 32 + b];
                    float g = tanh_(acc);
                    int u = 4 * bid + row;
                    float z = ldcgf(&g_z0[pidx(u, b)]);
                    float h = ldcgf(&g_h0[par][pidx(u, b)]);
                    stcgf(&g_h0[par ^ 1][pidx(u, b)], z * h + (1.f - z) * g);
                }
            } else {
                if (tau >= 1) {
                    int r2 = row - 4;
                    float acc = bias[20 + r2];
#pragma unroll
                    for (int kq = 0; kq < 32; ++kq) acc += pG1[(r2 * 32 + kq) * 32 + b];
                    float g = tanh_(acc);
                    int u = 4 * bid + r2;
                    float z = ldcgf(&g_z1[pidx(u, b)]);
                    float h = ldcgf(&g_h1[bn][pidx(u, b)]);
                    stcgf(&g_h1[tau & 1][pidx(u, b)], z * h + (1.f - z) * g);
                }
            }
        }
        bar_arrive();
        // ---- gap: next step's x dots (constant input; safe pre-barrier) ----
        if (wid < 4 && tau + 1 < Ssz) {
            int kq = wid;
            const float* xTn = g_xT + (long long)(tau + 1) * 4096;
            dotm<8, 4>(Wzr0 + kq * 32, 640, Wg0 + kq * 32, 640,
                       xTn + kq * 1024 + 4 * lane,
                       pZR0 + kq * 32 + lane, 640,
                       pG0 + kq * 32 + lane, 640);
        }
        bar_wait(++bar * NBLK);
    }

    // ---------------- Epilogue ----------------
    if (tid < 32) {
        int b = tid;
        float acc = bias[24];
        for (int k = 0; k < Hsz; ++k)
            acc = fmaf(Wy[k], ldcgf(&g_h1[0][pidx(k, b)]), acc);
        out[(b * Ssz + (Ssz - 1)) * Osz + bid] = acc;
    }
    {
        int i = bid * NTHR + tid;
        if (i < Bz * 2 * Hsz) {
            int b = i >> 10, rest = i & 1023;
            float v = (rest < Hsz) ? ldcgf(&g_h0[0][pidx(rest, b)])
                                   : ldcgf(&g_h1[0][pidx(rest - Hsz, b)]);
            out[Bz * Ssz * Osz + i] = v;
        }
    }
}

extern "C" void kernel_launch(void* const* d_in, const int* in_sizes, int n_in,
                              void* d_out, int out_size) {
    cudaFuncSetAttribute(gru_q,
                         cudaFuncAttributeMaxDynamicSharedMemorySize, SMEM_BYTES);
    prep_k<<<8192, 1024>>>((const float*)d_in[0]);
    gru_q<<<NBLK, NTHR, SMEM_BYTES>>>(
        (const float*)d_in[0], (const float*)d_in[1], (const float*)d_in[2],
        (const float*)d_in[3], (const float*)d_in[4], (const float*)d_in[5],
        (const float*)d_in[6], (const float*)d_in[7], (const float*)d_in[8],
        (const float*)d_in[9], (float*)d_out);
}

// round 12
// speedup vs baseline: 1.6319x; 1.0267x over previous
#include <cuda_runtime.h>

#define NBLK 128
#define NTHR 512
#define Bz   32
#define Ssz  2048
#define Isz  128
#define Hsz  512
#define Osz  128

#define PB_ZR0 32
#define PB_ZR1 5152
#define PB_G0  13344
#define PB_G1  15904
#define PB_Y   20000
#define OFF_W  20512
#define SMEM_FLOATS 40992
#define SMEM_BYTES (SMEM_FLOATS * 4)

// quad-interleaved k-major: idx(k,b) = (k>>2)*128 + 4b + (k&3)
__device__ float g_h0[2][Bz * Hsz];
__device__ float g_h1[2][Bz * Hsz];
__device__ float g_z0[Bz * Hsz];
__device__ float g_rh0[Bz * Hsz];
__device__ float g_z1[Bz * Hsz];
__device__ float g_rh1[Bz * Hsz];
__device__ float g_xT[(long long)Ssz * 128 * Bz];
__device__ unsigned g_count;

__device__ __forceinline__ int pidx(int k, int b) {
    return ((k >> 2) << 7) + (b << 2) + (k & 3);
}
__device__ __forceinline__ float4 ldcg128(const float* p) {
    float4 v;
    asm volatile("ld.global.cg.v4.f32 {%0,%1,%2,%3}, [%4];"
                 : "=f"(v.x), "=f"(v.y), "=f"(v.z), "=f"(v.w) : "l"(p));
    return v;
}
__device__ __forceinline__ float ldcgf(const float* p) {
    float v;
    asm volatile("ld.global.cg.f32 %0, [%1];" : "=f"(v) : "l"(p));
    return v;
}
__device__ __forceinline__ void stcgf(float* p, float v) {
    asm volatile("st.global.cg.f32 [%0], %1;" :: "l"(p), "f"(v));
}
__device__ __forceinline__ void bar_arrive() {
    __syncthreads();
    if (threadIdx.x == 0)
        asm volatile("red.release.gpu.add.u32 [%0], %1;"
                     :: "l"(&g_count), "r"(1u) : "memory");
}
__device__ __forceinline__ void bar_wait(unsigned target) {
    if (threadIdx.x == 0) {
        unsigned v;
        do {
            asm volatile("ld.acquire.gpu.u32 %0, [%1];"
                         : "=r"(v) : "l"(&g_count) : "memory");
        } while (v < target);
    }
    __syncthreads();
}
__device__ __forceinline__ float sigmoid_(float x) { return 1.0f / (1.0f + __expf(-x)); }
__device__ __forceinline__ float tanh_(float x)    { return 1.0f - 2.0f / (__expf(2.0f * x) + 1.0f); }
__device__ __forceinline__ unsigned long long f2(unsigned long long w,
                                                 unsigned long long s,
                                                 unsigned long long acc) {
    unsigned long long d;
    asm("fma.rn.f32x2 %0, %1, %2, %3;" : "=l"(d) : "l"(w), "l"(s), "l"(acc));
    return d;
}

// triple-merged job: R1+R2+R3 rows over one 32k state chunk (8x LDG.128 burst)
template <int R1, int R2, int R3>
__device__ __forceinline__ void dotm3(const float* __restrict__ wb1, int ws1,
                                      const float* __restrict__ wb2, int ws2,
                                      const float* __restrict__ wb3, int ws3,
                                      const float* __restrict__ sg,
                                      float* __restrict__ pd1, int prs1,
                                      float* __restrict__ pd2, int prs2,
                                      float* __restrict__ pd3, int prs3) {
    float4 s4[8];
#pragma unroll
    for (int p = 0; p < 8; ++p) s4[p] = ldcg128(sg + (p << 7));
    unsigned long long acc[R1 + R2 + R3];
#pragma unroll
    for (int i = 0; i < R1 + R2 + R3; ++i) acc[i] = 0ull;
#pragma unroll
    for (int p = 0; p < 8; ++p) {
        ulonglong2 sv = *(ulonglong2*)&s4[p];
#pragma unroll
        for (int r = 0; r < R1; ++r) {
            ulonglong2 wv = *(const ulonglong2*)(wb1 + r * ws1 + (p << 2));
            acc[r] = f2(wv.x, sv.x, acc[r]);
            acc[r] = f2(wv.y, sv.y, acc[r]);
        }
#pragma unroll
        for (int r = 0; r < R2; ++r) {
            ulonglong2 wv = *(const ulonglong2*)(wb2 + r * ws2 + (p << 2));
            acc[R1 + r] = f2(wv.x, sv.x, acc[R1 + r]);
            acc[R1 + r] = f2(wv.y, sv.y, acc[R1 + r]);
        }
#pragma unroll
        for (int r = 0; r < R3; ++r) {
            ulonglong2 wv = *(const ulonglong2*)(wb3 + r * ws3 + (p << 2));
            acc[R1 + R2 + r] = f2(wv.x, sv.x, acc[R1 + R2 + r]);
            acc[R1 + R2 + r] = f2(wv.y, sv.y, acc[R1 + R2 + r]);
        }
    }
#pragma unroll
    for (int r = 0; r < R1; ++r) { float2 a = *(float2*)&acc[r]; pd1[r * prs1] = a.x + a.y; }
#pragma unroll
    for (int r = 0; r < R2; ++r) { float2 a = *(float2*)&acc[R1 + r]; pd2[r * prs2] = a.x + a.y; }
#pragma unroll
    for (int r = 0; r < R3; ++r) { float2 a = *(float2*)&acc[R1 + R2 + r]; pd3[r * prs3] = a.x + a.y; }
}

__global__ void prep_k(const float* __restrict__ input) {
    long long idx = (long long)blockIdx.x * 1024 + threadIdx.x;
    if (idx == 0) g_count = 0u;
    if (idx < (long long)Bz * Ssz * Isz) {
        int b = (int)(idx >> 18);
        int rem = (int)(idx & 262143);
        int t = rem >> 7, k = rem & 127;
        g_xT[(long long)t * 4096 + pidx(k, b)] = input[idx];
    }
}

extern "C" __global__ void __launch_bounds__(NTHR, 1)
gru_w1(const float* __restrict__ input, const float* __restrict__ h0in,
       const float* __restrict__ Wx0, const float* __restrict__ Wh0,
       const float* __restrict__ bh0, const float* __restrict__ Wx1,
       const float* __restrict__ Wh1, const float* __restrict__ bh1,
       const float* __restrict__ Why, const float* __restrict__ bhy,
       float* __restrict__ out) {
    extern __shared__ float sm[];
    const int tid = threadIdx.x;
    const int bid = blockIdx.x;
    const int wid = tid >> 5, lane = tid & 31;

    float* bias = sm;
    float* pZR0 = sm + PB_ZR0;           // 8 x 20 slots (x:0-3, h:4-19)
    float* pZR1 = sm + PB_ZR1;           // 8 x 32 (h0:0-15, h1:16-31)
    float* pG0  = sm + PB_G0;            // 4 x 20 (x:0-3, h:4-19)
    float* pG1  = sm + PB_G1;            // 4 x 32 (x/h0':0-15, rh1:16-31)
    float* pY   = sm + PB_Y;             // 1 x 16
    float* Wzr0 = sm + OFF_W;            // 8 x 640
    float* Wg0  = Wzr0 + 5120;           // 4 x 640
    float* Wzr1 = Wg0 + 2560;            // 8 x 1024
    float* Wg1  = Wzr1 + 8192;           // 4 x 1024
    float* Wy   = Wg1 + 4096;            // 1 x 512

    for (int i = tid; i < 8 * 640; i += NTHR) {
        int r = i / 640, k = i - r * 640, j = 8 * bid + r;
        Wzr0[i] = (k < Isz) ? Wx0[j * Isz + k] : Wh0[j * Hsz + k - Isz];
    }
    for (int i = tid; i < 4 * 640; i += NTHR) {
        int r = i / 640, k = i - r * 640, j = 2 * Hsz + 4 * bid + r;
        Wg0[i] = (k < Isz) ? Wx0[j * Isz + k] : Wh0[j * Hsz + k - Isz];
    }
    for (int i = tid; i < 8 * 1024; i += NTHR) {
        int r = i >> 10, k = i & 1023, j = 8 * bid + r;
        Wzr1[i] = (k < Hsz) ? Wx1[j * Hsz + k] : Wh1[j * Hsz + k - Hsz];
    }
    for (int i = tid; i < 4 * 1024; i += NTHR) {
        int r = i >> 10, k = i & 1023, j = 2 * Hsz + 4 * bid + r;
        Wg1[i] = (k < Hsz) ? Wx1[j * Hsz + k] : Wh1[j * Hsz + k - Hsz];
    }
    for (int i = tid; i < Hsz; i += NTHR) Wy[i] = Why[bid * Hsz + i];
    if (tid < 8)       bias[tid] = bh0[8 * bid + tid];
    else if (tid < 12) bias[tid] = bh0[2 * Hsz + 4 * bid + tid - 8];
    else if (tid < 20) bias[tid] = bh1[8 * bid + tid - 12];
    else if (tid < 24) bias[tid] = bh1[2 * Hsz + 4 * bid + tid - 20];
    else if (tid == 24) bias[tid] = bhy[bid];

    {
        int i = bid * NTHR + tid;
        if (i < Bz * 2 * Hsz) {
            int b = i >> 10, rest = i & 1023;
            float v = h0in[i];
            if (rest < Hsz) stcgf(&g_h0[0][pidx(rest, b)], v);
            else            stcgf(&g_h1[0][pidx(rest - Hsz, b)], v);
        }
    }
    __syncthreads();
    // tau=0 gap-equivalent: x dots of step 0 (zr0-x + g0-x)
    if (wid < 4) {
        int kq = wid;
        dotm3<8, 4, 0>(Wzr0 + kq * 32, 640, Wg0 + kq * 32, 640, Wg0, 640,
                       g_xT + kq * 1024 + 4 * lane,
                       pZR0 + kq * 32 + lane, 640,
                       pG0 + kq * 32 + lane, 640, pG0, 640);
    }
    unsigned bar = 0;
    bar_arrive(); bar_wait(++bar * NBLK);

    for (int tau = 0; tau <= Ssz; ++tau) {
        const int par = tau & 1;            // h0 buffer (wavefront: L0 old == L1 in)
        const int bn = (tau + 1) & 1;       // h1_old buffer
        const float* h0c = g_h0[par];
        const float* h1o = g_h1[bn];

        // ================= W1: all heavy dots =================
        {
            int kq = wid;
            // job1: h0 chunk kq -> zr0-h(8) + zr1-h0(8) + g1-x(4)  [20 rows]
            dotm3<8, 8, 4>(Wzr0 + Isz + kq * 32, 640,
                           Wzr1 + kq * 32, 1024,
                           Wg1 + kq * 32, 1024,
                           h0c + kq * 1024 + 4 * lane,
                           pZR0 + (4 + kq) * 32 + lane, 640,
                           pZR1 + kq * 32 + lane, 1024,
                           pG1 + kq * 32 + lane, 1024);
            // job2: h1 chunk kq -> zr1-h1(8) + y(1)  [9 rows]
            dotm3<8, 1, 0>(Wzr1 + 512 + kq * 32, 1024,
                           Wy + kq * 32, 512, Wy, 512,
                           h1o + kq * 1024 + 4 * lane,
                           pZR1 + (16 + kq) * 32 + lane, 1024,
                           pY + kq * 32 + lane, 1, pY + lane, 1);
        }
        __syncthreads();
        for (int idx = tid; idx < 544; idx += NTHR) {
            int row = idx >> 5, b = idx & 31;
            if (row < 8) {
                if (tau < Ssz) {
                    float acc = bias[row];
#pragma unroll
                    for (int kq = 0; kq < 20; ++kq) acc += pZR0[(row * 20 + kq) * 32 + b];
                    float s = sigmoid_(acc);
                    int j = 8 * bid + row;
                    if (j < Hsz) stcgf(&g_z0[pidx(j, b)], s);
                    else stcgf(&g_rh0[pidx(j - Hsz, b)],
                               s * ldcgf(&g_h0[par][pidx(j - Hsz, b)]));
                }
            } else if (row < 16) {
                if (tau >= 1) {
                    int r2 = row - 8;
                    float acc = bias[12 + r2];
#pragma unroll
                    for (int kq = 0; kq < 32; ++kq) acc += pZR1[(r2 * 32 + kq) * 32 + b];
                    float s = sigmoid_(acc);
                    int j = 8 * bid + r2;
                    if (j < Hsz) stcgf(&g_z1[pidx(j, b)], s);
                    else stcgf(&g_rh1[pidx(j - Hsz, b)],
                               s * ldcgf(&g_h1[bn][pidx(j - Hsz, b)]));
                }
            } else {
                if (tau >= 2) {
                    float acc = bias[24];
#pragma unroll
                    for (int kq = 0; kq < 16; ++kq) acc += pY[kq * 32 + b];
                    out[(b * Ssz + (tau - 2)) * Osz + bid] = acc;
                }
            }
        }
        bar_arrive(); bar_wait(++bar * NBLK);

        // ================= W2: g-gate h-side dots =================
        {
            int kq = wid;
            if (tau < Ssz)   // g0-h (4r) on rh0 chunk kq
                dotm3<4, 0, 0>(Wg0 + Isz + kq * 32, 640, Wg0, 640, Wg0, 640,
                               g_rh0 + kq * 1024 + 4 * lane,
                               pG0 + (4 + kq) * 32 + lane, 640,
                               pG0, 640, pG0, 640);
            if (tau >= 1)    // g1-h (4r) on rh1 chunk kq
                dotm3<4, 0, 0>(Wg1 + 512 + kq * 32, 1024, Wg1, 1024, Wg1, 1024,
                               g_rh1 + kq * 1024 + 4 * lane,
                               pG1 + (16 + kq) * 32 + lane, 1024,
                               pG1, 1024, pG1, 1024);
        }
        __syncthreads();
        if (tid < 256) {
            int row = tid >> 5, b = tid & 31;
            if (row < 4) {
                if (tau < Ssz) {
                    float acc = bias[8 + row];
#pragma unroll
                    for (int kq = 0; kq < 20; ++kq) acc += pG0[(row * 20 + kq) * 32 + b];
                    float g = tanh_(acc);
                    int u = 4 * bid + row;
                    float z = ldcgf(&g_z0[pidx(u, b)]);
                    float h = ldcgf(&g_h0[par][pidx(u, b)]);
                    stcgf(&g_h0[par ^ 1][pidx(u, b)], z * h + (1.f - z) * g);
                }
            } else {
                if (tau >= 1) {
                    int r2 = row - 4;
                    float acc = bias[20 + r2];
#pragma unroll
                    for (int kq = 0; kq < 32; ++kq) acc += pG1[(r2 * 32 + kq) * 32 + b];
                    float g = tanh_(acc);
                    int u = 4 * bid + r2;
                    float z = ldcgf(&g_z1[pidx(u, b)]);
                    float h = ldcgf(&g_h1[bn][pidx(u, b)]);
                    stcgf(&g_h1[tau & 1][pidx(u, b)], z * h + (1.f - z) * g);
                }
            }
        }
        bar_arrive();
        // ---- gap: next step's x dots (constant input; safe pre-barrier) ----
        if (wid < 4 && tau + 1 < Ssz) {
            int kq = wid;
            const float* xTn = g_xT + (long long)(tau + 1) * 4096;
            dotm3<8, 4, 0>(Wzr0 + kq * 32, 640, Wg0 + kq * 32, 640, Wg0, 640,
                           xTn + kq * 1024 + 4 * lane,
                           pZR0 + kq * 32 + lane, 640,
                           pG0 + kq * 32 + lane, 640, pG0, 640);
        }
        bar_wait(++bar * NBLK);
    }

    // ---------------- Epilogue ----------------
    if (tid < 32) {
        int b = tid;
        float acc = bias[24];
        for (int k = 0; k < Hsz; ++k)
            acc = fmaf(Wy[k], ldcgf(&g_h1[0][pidx(k, b)]), acc);
        out[(b * Ssz + (Ssz - 1)) * Osz + bid] = acc;
    }
    {
        int i = bid * NTHR + tid;
        if (i < Bz * 2 * Hsz) {
            int b = i >> 10, rest = i & 1023;
            float v = (rest < Hsz) ? ldcgf(&g_h0[0][pidx(rest, b)])
                                   : ldcgf(&g_h1[0][pidx(rest - Hsz, b)]);
            out[Bz * Ssz * Osz + i] = v;
        }
    }
}

extern "C" void kernel_launch(void* const* d_in, const int* in_sizes, int n_in,
                              void* d_out, int out_size) {
    cudaFuncSetAttribute(gru_w1,
                         cudaFuncAttributeMaxDynamicSharedMemorySize, SMEM_BYTES);
    prep_k<<<8192, 1024>>>((const float*)d_in[0]);
    gru_w1<<<NBLK, NTHR, SMEM_BYTES>>>(
        (const float*)d_in[0], (const float*)d_in[1], (const float*)d_in[2],
        (const float*)d_in[3], (const float*)d_in[4], (const float*)d_in[5],
        (const float*)d_in[6], (const float*)d_in[7], (const float*)d_in[8],
        (const float*)d_in[9], (float*)d_out);
}

// round 13
// speedup vs baseline: 1.7340x; 1.0625x over previous
#include <cuda_runtime.h>

#define NBLK 128
#define NTHR 512
#define Bz   32
#define Ssz  2048
#define Isz  128
#define Hsz  512
#define Osz  128

#define PB_ZR0 32
#define PB_ZR1 5152
#define PB_G0  13344
#define PB_G1  15904
#define PB_Y   20000
#define OFF_W  20512
#define SMEM_FLOATS 40992
#define SMEM_BYTES (SMEM_FLOATS * 4)

// quad-interleaved k-major: idx(k,b) = (k>>2)*128 + 4b + (k&3)
__device__ float g_h0[2][Bz * Hsz];
__device__ float g_h1[2][Bz * Hsz];
__device__ float g_z0[Bz * Hsz];
__device__ float g_rh0[Bz * Hsz];
__device__ float g_z1[Bz * Hsz];
__device__ float g_rh1[Bz * Hsz];
__device__ float g_xT[(long long)Ssz * 128 * Bz];
__device__ unsigned g_count;

__device__ __forceinline__ int pidx(int k, int b) {
    return ((k >> 2) << 7) + (b << 2) + (k & 3);
}
__device__ __forceinline__ float4 ldcg128(const float* p) {
    float4 v;
    asm volatile("ld.global.cg.v4.f32 {%0,%1,%2,%3}, [%4];"
                 : "=f"(v.x), "=f"(v.y), "=f"(v.z), "=f"(v.w) : "l"(p));
    return v;
}
__device__ __forceinline__ float ldcgf(const float* p) {
    float v;
    asm volatile("ld.global.cg.f32 %0, [%1];" : "=f"(v) : "l"(p));
    return v;
}
__device__ __forceinline__ void stcgf(float* p, float v) {
    asm volatile("st.global.cg.f32 [%0], %1;" :: "l"(p), "f"(v));
}
__device__ __forceinline__ void bar_arrive() {
    __syncthreads();
    if (threadIdx.x == 0)
        asm volatile("red.release.gpu.add.u32 [%0], %1;"
                     :: "l"(&g_count), "r"(1u) : "memory");
}
__device__ __forceinline__ void bar_wait(unsigned target) {
    if (threadIdx.x == 0) {
        unsigned v;
        do {
            asm volatile("ld.acquire.gpu.u32 %0, [%1];"
                         : "=r"(v) : "l"(&g_count) : "memory");
        } while (v < target);
    }
    __syncthreads();
}
__device__ __forceinline__ float sigmoid_(float x) { return 1.0f / (1.0f + __expf(-x)); }
__device__ __forceinline__ float tanh_(float x)    { return 1.0f - 2.0f / (__expf(2.0f * x) + 1.0f); }
__device__ __forceinline__ unsigned long long f2(unsigned long long w,
                                                 unsigned long long s,
                                                 unsigned long long acc) {
    unsigned long long d;
    asm("fma.rn.f32x2 %0, %1, %2, %3;" : "=l"(d) : "l"(w), "l"(s), "l"(acc));
    return d;
}

__device__ __forceinline__ void burst8(float4* s4, const float* sg) {
#pragma unroll
    for (int p = 0; p < 8; ++p) s4[p] = ldcg128(sg + (p << 7));
}

// compute-only triple-merged dot on preloaded state chunk
template <int R1, int R2, int R3>
__device__ __forceinline__ void dotc(const float4* __restrict__ s4,
                                     const float* __restrict__ wb1, int ws1,
                                     const float* __restrict__ wb2, int ws2,
                                     const float* __restrict__ wb3, int ws3,
                                     float* __restrict__ pd1, int prs1,
                                     float* __restrict__ pd2, int prs2,
                                     float* __restrict__ pd3, int prs3) {
    unsigned long long acc[R1 + R2 + R3];
#pragma unroll
    for (int i = 0; i < R1 + R2 + R3; ++i) acc[i] = 0ull;
#pragma unroll
    for (int p = 0; p < 8; ++p) {
        ulonglong2 sv = *(ulonglong2*)&s4[p];
#pragma unroll
        for (int r = 0; r < R1; ++r) {
            ulonglong2 wv = *(const ulonglong2*)(wb1 + r * ws1 + (p << 2));
            acc[r] = f2(wv.x, sv.x, acc[r]);
            acc[r] = f2(wv.y, sv.y, acc[r]);
        }
#pragma unroll
        for (int r = 0; r < R2; ++r) {
            ulonglong2 wv = *(const ulonglong2*)(wb2 + r * ws2 + (p << 2));
            acc[R1 + r] = f2(wv.x, sv.x, acc[R1 + r]);
            acc[R1 + r] = f2(wv.y, sv.y, acc[R1 + r]);
        }
#pragma unroll
        for (int r = 0; r < R3; ++r) {
            ulonglong2 wv = *(const ulonglong2*)(wb3 + r * ws3 + (p << 2));
            acc[R1 + R2 + r] = f2(wv.x, sv.x, acc[R1 + R2 + r]);
            acc[R1 + R2 + r] = f2(wv.y, sv.y, acc[R1 + R2 + r]);
        }
    }
#pragma unroll
    for (int r = 0; r < R1; ++r) { float2 a = *(float2*)&acc[r]; pd1[r * prs1] = a.x + a.y; }
#pragma unroll
    for (int r = 0; r < R2; ++r) { float2 a = *(float2*)&acc[R1 + r]; pd2[r * prs2] = a.x + a.y; }
#pragma unroll
    for (int r = 0; r < R3; ++r) { float2 a = *(float2*)&acc[R1 + R2 + r]; pd3[r * prs3] = a.x + a.y; }
}

template <int R1, int R2, int R3>
__device__ __forceinline__ void dotm3(const float* __restrict__ wb1, int ws1,
                                      const float* __restrict__ wb2, int ws2,
                                      const float* __restrict__ wb3, int ws3,
                                      const float* __restrict__ sg,
                                      float* __restrict__ pd1, int prs1,
                                      float* __restrict__ pd2, int prs2,
                                      float* __restrict__ pd3, int prs3) {
    float4 s4[8];
    burst8(s4, sg);
    dotc<R1, R2, R3>(s4, wb1, ws1, wb2, ws2, wb3, ws3, pd1, prs1, pd2, prs2, pd3, prs3);
}

__global__ void prep_k(const float* __restrict__ input) {
    long long idx = (long long)blockIdx.x * 1024 + threadIdx.x;
    if (idx == 0) g_count = 0u;
    if (idx < (long long)Bz * Ssz * Isz) {
        int b = (int)(idx >> 18);
        int rem = (int)(idx & 262143);
        int t = rem >> 7, k = rem & 127;
        g_xT[(long long)t * 4096 + pidx(k, b)] = input[idx];
    }
}

extern "C" __global__ void __launch_bounds__(NTHR, 1)
gru_cp(const float* __restrict__ input, const float* __restrict__ h0in,
       const float* __restrict__ Wx0, const float* __restrict__ Wh0,
       const float* __restrict__ bh0, const float* __restrict__ Wx1,
       const float* __restrict__ Wh1, const float* __restrict__ bh1,
       const float* __restrict__ Why, const float* __restrict__ bhy,
       float* __restrict__ out) {
    extern __shared__ float sm[];
    const int tid = threadIdx.x;
    const int bid = blockIdx.x;
    const int wid = tid >> 5, lane = tid & 31;

    float* bias = sm;
    float* pZR0 = sm + PB_ZR0;           // 8 x 20 (x:0-3, h:4-19)
    float* pZR1 = sm + PB_ZR1;           // 8 x 32 (h0:0-15, h1:16-31)
    float* pG0  = sm + PB_G0;            // 4 x 20 (x:0-3, h:4-19)
    float* pG1  = sm + PB_G1;            // 4 x 32 (x:0-15, rh1:16-31)
    float* pY   = sm + PB_Y;             // 1 x 16
    float* Wzr0 = sm + OFF_W;            // 8 x 640
    float* Wg0  = Wzr0 + 5120;           // 4 x 640
    float* Wzr1 = Wg0 + 2560;            // 8 x 1024
    float* Wg1  = Wzr1 + 8192;           // 4 x 1024
    float* Wy   = Wg1 + 4096;            // 1 x 512

    for (int i = tid; i < 8 * 640; i += NTHR) {
        int r = i / 640, k = i - r * 640, j = 8 * bid + r;
        Wzr0[i] = (k < Isz) ? Wx0[j * Isz + k] : Wh0[j * Hsz + k - Isz];
    }
    for (int i = tid; i < 4 * 640; i += NTHR) {
        int r = i / 640, k = i - r * 640, j = 2 * Hsz + 4 * bid + r;
        Wg0[i] = (k < Isz) ? Wx0[j * Isz + k] : Wh0[j * Hsz + k - Isz];
    }
    for (int i = tid; i < 8 * 1024; i += NTHR) {
        int r = i >> 10, k = i & 1023, j = 8 * bid + r;
        Wzr1[i] = (k < Hsz) ? Wx1[j * Hsz + k] : Wh1[j * Hsz + k - Hsz];
    }
    for (int i = tid; i < 4 * 1024; i += NTHR) {
        int r = i >> 10, k = i & 1023, j = 2 * Hsz + 4 * bid + r;
        Wg1[i] = (k < Hsz) ? Wx1[j * Hsz + k] : Wh1[j * Hsz + k - Hsz];
    }
    for (int i = tid; i < Hsz; i += NTHR) Wy[i] = Why[bid * Hsz + i];
    if (tid < 8)       bias[tid] = bh0[8 * bid + tid];
    else if (tid < 12) bias[tid] = bh0[2 * Hsz + 4 * bid + tid - 8];
    else if (tid < 20) bias[tid] = bh1[8 * bid + tid - 12];
    else if (tid < 24) bias[tid] = bh1[2 * Hsz + 4 * bid + tid - 20];
    else if (tid == 24) bias[tid] = bhy[bid];

    {
        int i = bid * NTHR + tid;
        if (i < Bz * 2 * Hsz) {
            int b = i >> 10, rest = i & 1023;
            float v = h0in[i];
            if (rest < Hsz) stcgf(&g_h0[0][pidx(rest, b)], v);
            else            stcgf(&g_h1[0][pidx(rest - Hsz, b)], v);
        }
    }
    __syncthreads();
    if (wid < 4) {   // tau=0 x dots
        int kq = wid;
        dotm3<8, 4, 0>(Wzr0 + kq * 32, 640, Wg0 + kq * 32, 640, Wg0, 640,
                       g_xT + kq * 1024 + 4 * lane,
                       pZR0 + kq * 32 + lane, 640,
                       pG0 + kq * 32 + lane, 640, pG0, 640);
    }
    unsigned bar = 0;
    bar_arrive(); bar_wait(++bar * NBLK);

    for (int tau = 0; tau <= Ssz; ++tau) {
        const int par = tau & 1;
        const int bn = (tau + 1) & 1;
        const float* h0c = g_h0[par];
        const float* h1o = g_h1[bn];

        // ======== W1: prefetch reduce operands, dual burst, dots ========
        float preh1 = 0.f;
        {
            int row = tid >> 5, b = tid & 31;   // row 0..15
            if (row < 8) {
                int j = 8 * bid + row;
                if (j >= Hsz) preh1 = ldcgf(&h0c[pidx(j - Hsz, b)]);
            } else {
                int j = 8 * bid + (row - 8);
                if (j >= Hsz) preh1 = ldcgf(&h1o[pidx(j - Hsz, b)]);
            }
        }
        {
            int kq = wid;
            float4 sA[8], sB[8];
            burst8(sA, h0c + kq * 1024 + 4 * lane);
            burst8(sB, h1o + kq * 1024 + 4 * lane);
            // job1: zr0-h(8) + zr1-h0(8) + g1-x(4) on h0 chunk
            dotc<8, 8, 4>(sA,
                          Wzr0 + Isz + kq * 32, 640,
                          Wzr1 + kq * 32, 1024,
                          Wg1 + kq * 32, 1024,
                          pZR0 + (4 + kq) * 32 + lane, 640,
                          pZR1 + kq * 32 + lane, 1024,
                          pG1 + kq * 32 + lane, 1024);
            // job2: zr1-h1(8) + y(1) on h1 chunk
            dotc<8, 1, 0>(sB,
                          Wzr1 + 512 + kq * 32, 1024,
                          Wy + kq * 32, 512, Wy, 512,
                          pZR1 + (16 + kq) * 32 + lane, 1024,
                          pY + kq * 32 + lane, 1, pY + lane, 1);
        }
        __syncthreads();
        {
            int row = tid >> 5, b = tid & 31;
            if (row < 8) {
                if (tau < Ssz) {
                    float acc = bias[row];
#pragma unroll
                    for (int kq = 0; kq < 20; ++kq) acc += pZR0[(row * 20 + kq) * 32 + b];
                    float s = sigmoid_(acc);
                    int j = 8 * bid + row;
                    if (j < Hsz) stcgf(&g_z0[pidx(j, b)], s);
                    else         stcgf(&g_rh0[pidx(j - Hsz, b)], s * preh1);
                }
            } else {
                if (tau >= 1) {
                    int r2 = row - 8;
                    float acc = bias[12 + r2];
#pragma unroll
                    for (int kq = 0; kq < 32; ++kq) acc += pZR1[(r2 * 32 + kq) * 32 + b];
                    float s = sigmoid_(acc);
                    int j = 8 * bid + r2;
                    if (j < Hsz) stcgf(&g_z1[pidx(j, b)], s);
                    else         stcgf(&g_rh1[pidx(j - Hsz, b)], s * preh1);
                }
            }
            if (tid < 32 && tau >= 2) {
                float acc = bias[24];
#pragma unroll
                for (int kq = 0; kq < 16; ++kq) acc += pY[kq * 32 + tid];
                out[(tid * Ssz + (tau - 2)) * Osz + bid] = acc;
            }
        }
        bar_arrive(); bar_wait(++bar * NBLK);

        // ======== W2: prefetch z/h, g-gate dots ========
        float prez = 0.f, preh2 = 0.f;
        if (tid < 256) {
            int row = tid >> 5, b = tid & 31;
            if (row < 4) {
                int u = 4 * bid + row;
                prez  = ldcgf(&g_z0[pidx(u, b)]);
                preh2 = ldcgf(&h0c[pidx(u, b)]);
            } else {
                int u = 4 * bid + (row - 4);
                prez  = ldcgf(&g_z1[pidx(u, b)]);
                preh2 = ldcgf(&h1o[pidx(u, b)]);
            }
        }
        {
            int kq = wid;
            if (tau < Ssz)
                dotm3<4, 0, 0>(Wg0 + Isz + kq * 32, 640, Wg0, 640, Wg0, 640,
                               g_rh0 + kq * 1024 + 4 * lane,
                               pG0 + (4 + kq) * 32 + lane, 640,
                               pG0, 640, pG0, 640);
            if (tau >= 1)
                dotm3<4, 0, 0>(Wg1 + 512 + kq * 32, 1024, Wg1, 1024, Wg1, 1024,
                               g_rh1 + kq * 1024 + 4 * lane,
                               pG1 + (16 + kq) * 32 + lane, 1024,
                               pG1, 1024, pG1, 1024);
        }
        __syncthreads();
        if (tid < 256) {
            int row = tid >> 5, b = tid & 31;
            if (row < 4) {
                if (tau < Ssz) {
                    float acc = bias[8 + row];
#pragma unroll
                    for (int kq = 0; kq < 20; ++kq) acc += pG0[(row * 20 + kq) * 32 + b];
                    float g = tanh_(acc);
                    int u = 4 * bid + row;
                    stcgf(&g_h0[par ^ 1][pidx(u, b)], prez * preh2 + (1.f - prez) * g);
                }
            } else {
                if (tau >= 1) {
                    int r2 = row - 4;
                    float acc = bias[20 + r2];
#pragma unroll
                    for (int kq = 0; kq < 32; ++kq) acc += pG1[(r2 * 32 + kq) * 32 + b];
                    float g = tanh_(acc);
                    int u = 4 * bid + r2;
                    stcgf(&g_h1[tau & 1][pidx(u, b)], prez * preh2 + (1.f - prez) * g);
                }
            }
        }
        bar_arrive();
        if (wid < 4 && tau + 1 < Ssz) {   // gap: next step's x dots
            int kq = wid;
            const float* xTn = g_xT + (long long)(tau + 1) * 4096;
            dotm3<8, 4, 0>(Wzr0 + kq * 32, 640, Wg0 + kq * 32, 640, Wg0, 640,
                           xTn + kq * 1024 + 4 * lane,
                           pZR0 + kq * 32 + lane, 640,
                           pG0 + kq * 32 + lane, 640, pG0, 640);
        }
        bar_wait(++bar * NBLK);
    }

    // ---------------- Epilogue ----------------
    if (tid < 32) {
        int b = tid;
        float acc = bias[24];
        for (int k = 0; k < Hsz; ++k)
            acc = fmaf(Wy[k], ldcgf(&g_h1[0][pidx(k, b)]), acc);
        out[(b * Ssz + (Ssz - 1)) * Osz + bid] = acc;
    }
    {
        int i = bid * NTHR + tid;
        if (i < Bz * 2 * Hsz) {
            int b = i >> 10, rest = i & 1023;
            float v = (rest < Hsz) ? ldcgf(&g_h0[0][pidx(rest, b)])
                                   : ldcgf(&g_h1[0][pidx(rest - Hsz, b)]);
            out[Bz * Ssz * Osz + i] = v;
        }
    }
}

extern "C" void kernel_launch(void* const* d_in, const int* in_sizes, int n_in,
                              void* d_out, int out_size) {
    cudaFuncSetAttribute(gru_cp,
                         cudaFuncAttributeMaxDynamicSharedMemorySize, SMEM_BYTES);
    prep_k<<<8192, 1024>>>((const float*)d_in[0]);
    gru_cp<<<NBLK, NTHR, SMEM_BYTES>>>(
        (const float*)d_in[0], (const float*)d_in[1], (const float*)d_in[2],
        (const float*)d_in[3], (const float*)d_in[4], (const float*)d_in[5],
        (const float*)d_in[6], (const float*)d_in[7], (const float*)d_in[8],
        (const float*)d_in[9], (float*)d_out);
}